// round 1
// baseline (speedup 1.0000x reference)
#include <cuda_runtime.h>
#include <cstdint>

// ---------------------------------------------------------------------------
// ElementwiseTensorProducts: fused per-tile kernel.
//   Stage 1: P0 = z0 @ [W0l;W0r]^T + [b0l;b0r]           (M=32,  N=128, K=128)
//   Stage 2: P1 = z1 @ [W1l;W1r]^T                        (M=96,  N=128, K=128)
//   Stage 3: Y0 = [p00 | p110] ;  out0 = Y0 @ W0o^T + b0o (M=32,  N=128, K=128)
//   Stage 4: Y1_i = [q011|q101|q111] ; out1_i = Y1_i @ W1o^T (M=32, N=128, K=192) x3
// All GEMMs use f32x2 packed FMA (FFMA2) with K-packed accumulator pairs.
// ---------------------------------------------------------------------------

namespace {
constexpr int BN   = 65536;   // B*N tokens
constexpr int TOK  = 32;      // tokens per CTA
constexpr int NT   = 256;     // threads per CTA
constexpr int P128 = 132;     // padded row stride for K=128 tiles (floats)
constexpr int P192 = 196;     // padded row stride for K=192 tiles (floats)

constexpr int SW_F  = 128 * P192;   // weight buffer (max: W1o 128x192) = 25088
constexpr int SB_F  = 96 * P128;    // X/Y staging (max: z1 tile 96x128) = 12672
constexpr int SP0_F = TOK * P128;   // P0: 32x128                        = 4224
constexpr int SP1_F = 96 * P128;    // P1: 96x128                        = 12672
constexpr int SMEM_F = SW_F + SB_F + SP0_F + SP1_F;           // 54656 floats
constexpr int SMEM_BYTES = SMEM_F * 4;                        // 218624 bytes
}

using ull = unsigned long long;

__device__ __forceinline__ void ffma2(ull& d, ull a, ull b) {
    // packed f32x2 fma: d.lo += a.lo*b.lo ; d.hi += a.hi*b.hi
    asm volatile("fma.rn.f32x2 %0, %1, %2, %0;" : "+l"(d) : "l"(a), "l"(b));
}

__device__ __forceinline__ float hsum2(ull v) {
    float lo, hi;
    asm("mov.b64 {%0, %1}, %2;" : "=f"(lo), "=f"(hi) : "l"(v));
    return lo + hi;
}

// Copy a ROWSxCOLS row-major tile from global into smem with padded stride.
template<int ROWS, int COLS, int PADV>
__device__ __forceinline__ void copy_tile(const float* __restrict__ g,
                                          float* __restrict__ s) {
    constexpr int N4 = ROWS * COLS / 4;
    constexpr int C4 = COLS / 4;
    for (int idx = threadIdx.x; idx < N4; idx += NT) {
        int r = idx / C4;
        int c = idx - r * C4;
        float4 v = *reinterpret_cast<const float4*>(g + (long long)r * COLS + c * 4);
        *reinterpret_cast<float4*>(s + r * PADV + c * 4) = v;
    }
}

// Register-tiled GEMM over smem operands, K-packed f32x2 accumulation.
// res[i][j] = sum_k A[m0+i][k] * W[og + j*NOG][k]
template<int K, int PADA, int PADW, int TM, int TN, int NOG>
__device__ __forceinline__ void gemm_core(const float* __restrict__ A,
                                          const float* __restrict__ W,
                                          int m0, int og, float (&res)[TM][TN]) {
    ull acc[TM][TN];
#pragma unroll
    for (int i = 0; i < TM; i++)
#pragma unroll
        for (int j = 0; j < TN; j++) acc[i][j] = 0ull;

#pragma unroll 4
    for (int k4 = 0; k4 < K / 4; k4++) {
        ulonglong2 a[TM], b[TN];
#pragma unroll
        for (int i = 0; i < TM; i++)
            a[i] = *reinterpret_cast<const ulonglong2*>(A + (m0 + i) * PADA + k4 * 4);
#pragma unroll
        for (int j = 0; j < TN; j++)
            b[j] = *reinterpret_cast<const ulonglong2*>(W + (og + j * NOG) * PADW + k4 * 4);
#pragma unroll
        for (int i = 0; i < TM; i++)
#pragma unroll
            for (int j = 0; j < TN; j++) {
                ffma2(acc[i][j], a[i].x, b[j].x);
                ffma2(acc[i][j], a[i].y, b[j].y);
            }
    }
#pragma unroll
    for (int i = 0; i < TM; i++)
#pragma unroll
        for (int j = 0; j < TN; j++) res[i][j] = hsum2(acc[i][j]);
}

__global__ __launch_bounds__(NT, 1)
void etp_kernel(const float* __restrict__ z0,  const float* __restrict__ z1,
                const float* __restrict__ W0l, const float* __restrict__ b0l,
                const float* __restrict__ W0r, const float* __restrict__ b0r,
                const float* __restrict__ W1l, const float* __restrict__ W1r,
                const float* __restrict__ W0o, const float* __restrict__ b0o,
                const float* __restrict__ W1o, float* __restrict__ out) {
    extern __shared__ float sm[];
    float* sW  = sm;             // staged weights (per stage)
    float* sB  = sW + SW_F;      // X / Y staging
    float* sP0 = sB + SB_F;      // projections of z0  (32 x 128, l|r)
    float* sP1 = sP0 + SP0_F;    // projections of z1  (96 x 128, l|r), row = 3t+i

    const int tid = threadIdx.x;
    const int t0  = blockIdx.x * TOK;
    float* out0 = out;
    float* out1 = out + (long long)BN * 128;

    // ---- Stage 1: load W0l/W0r + z0 tile, GEMM1 -> P0 (+bias) -------------
    copy_tile<64, 128, P128>(W0l, sW);
    copy_tile<64, 128, P128>(W0r, sW + 64 * P128);
    copy_tile<TOK, 128, P128>(z0 + (long long)t0 * 128, sB);
    __syncthreads();
    {
        const int og = tid & 31, tg = tid >> 5, m0 = tg * 4;
        float rv[4][4];
        gemm_core<128, P128, P128, 4, 4, 32>(sB, sW, m0, og, rv);
#pragma unroll
        for (int i = 0; i < 4; i++)
#pragma unroll
            for (int j = 0; j < 4; j++) {
                int n = og + j * 32;
                float bias = (n < 64) ? b0l[n] : b0r[n - 64];
                sP0[(m0 + i) * P128 + n] = rv[i][j] + bias;
            }
    }
    __syncthreads();

    // ---- Stage 2: load W1l/W1r + z1 tile (96 rows), GEMM2 -> P1 -----------
    copy_tile<64, 128, P128>(W1l, sW);
    copy_tile<64, 128, P128>(W1r, sW + 64 * P128);
    copy_tile<96, 128, P128>(z1 + (long long)t0 * 3 * 128, sB);
    __syncthreads();
    {
        const int og = tid & 15, tg = tid >> 4, m0 = tg * 6;
        float rv[6][8];
        gemm_core<128, P128, P128, 6, 8, 16>(sB, sW, m0, og, rv);
#pragma unroll
        for (int i = 0; i < 6; i++)
#pragma unroll
            for (int j = 0; j < 8; j++)
                sP1[(m0 + i) * P128 + og + j * 16] = rv[i][j];
    }
    __syncthreads();

    // ---- Stage 3: elementwise Y0 = [p00 | p110] into sB; load W0o ---------
    for (int idx = tid; idx < TOK * 64; idx += NT) {
        int t = idx >> 6, r = idx & 63;
        const float* p0 = sP0 + t * P128;
        const float* p1 = sP1 + 3 * t * P128;
        sB[t * P128 + r] = p0[r] * p0[64 + r];
        float s = p1[r]            * p1[64 + r]
                + p1[P128 + r]     * p1[P128 + 64 + r]
                + p1[2 * P128 + r] * p1[2 * P128 + 64 + r];
        sB[t * P128 + 64 + r] = s;
    }
    copy_tile<128, 128, P128>(W0o, sW);
    __syncthreads();

    // GEMM3: out0 = Y0 @ W0o^T + b0o
    {
        const int og = tid & 31, tg = tid >> 5, m0 = tg * 4;
        float rv[4][4];
        gemm_core<128, P128, P128, 4, 4, 32>(sB, sW, m0, og, rv);
#pragma unroll
        for (int i = 0; i < 4; i++)
#pragma unroll
            for (int j = 0; j < 4; j++) {
                int n = og + j * 32;
                out0[(long long)(t0 + m0 + i) * 128 + n] = rv[i][j] + b0o[n];
            }
    }
    __syncthreads();

    // ---- Stage 4: W1o once; per i: Y1_i = [q011|q101|q111], GEMM4 -> out1 -
    copy_tile<128, 192, P192>(W1o, sW);

#pragma unroll 1
    for (int ic = 0; ic < 3; ic++) {
        const int i1 = (ic + 1) == 3 ? 0 : ic + 1;   // (ic+1)%3
        const int i2 = (ic + 2) >= 3 ? ic - 1 : ic + 2; // (ic+2)%3
        for (int idx = tid; idx < TOK * 64; idx += NT) {
            int t = idx >> 6, r = idx & 63;
            const float* p0 = sP0 + t * P128;
            const float* p1 = sP1 + 3 * t * P128;
            float q011 = p0[r] * p1[ic * P128 + 64 + r];
            float q101 = p1[ic * P128 + r] * p0[64 + r];
            float q111 = p1[i1 * P128 + r] * p1[i2 * P128 + 64 + r]
                       - p1[i2 * P128 + r] * p1[i1 * P128 + 64 + r];
            float* y = sB + t * P192;
            y[r]       = q011;
            y[64 + r]  = q101;
            y[128 + r] = q111;
        }
        __syncthreads();
        {
            const int og = tid & 31, tg = tid >> 5, m0 = tg * 4;
            float rv[4][4];
            gemm_core<192, P192, P192, 4, 4, 32>(sB, sW, m0, og, rv);
#pragma unroll
            for (int i = 0; i < 4; i++)
#pragma unroll
                for (int j = 0; j < 4; j++) {
                    int n = og + j * 32;
                    out1[(long long)(t0 + m0 + i) * 384 + ic * 128 + n] = rv[i][j];
                }
        }
        __syncthreads();
    }
}

extern "C" void kernel_launch(void* const* d_in, const int* in_sizes, int n_in,
                              void* d_out, int out_size) {
    (void)in_sizes; (void)n_in; (void)out_size;
    cudaFuncSetAttribute(etp_kernel, cudaFuncAttributeMaxDynamicSharedMemorySize,
                         SMEM_BYTES);
    etp_kernel<<<BN / TOK, NT, SMEM_BYTES>>>(
        (const float*)d_in[0],  (const float*)d_in[1],
        (const float*)d_in[2],  (const float*)d_in[3],
        (const float*)d_in[4],  (const float*)d_in[5],
        (const float*)d_in[6],  (const float*)d_in[7],
        (const float*)d_in[8],  (const float*)d_in[9],
        (const float*)d_in[10], (float*)d_out);
}

// round 3
// speedup vs baseline: 1.6709x; 1.6709x over previous
#include <cuda_runtime.h>
#include <cuda_bf16.h>
#include <cstdint>

// ===========================================================================
// ElementwiseTensorProducts on tcgen05 (sm_103a) with safe fallback.
//   - etp_tc: tensor-core path, body compiled only under the sm_103a feature
//     target (the harness also runs a plain sm_103 pass where tcgen05 is
//     illegal -> body becomes a stub there).
//   - probe_tc sets g_tc_ok=1 only in the feature binary.
//   - etp_fb: round-1 FFMA2 kernel, early-exits when g_tc_ok==1.
// ===========================================================================

#if defined(__CUDA_ARCH_FEAT_SM103_ALL) || defined(__CUDA_ARCH_FEAT_SM100_ALL) || \
    defined(__CUDA_ARCH_FEAT_SM101_ALL) || defined(__CUDA_ARCH_SPECIFIC__) ||     \
    defined(__CUDA_ARCH_FAMILY_SPECIFIC__)
#define ETP_TC_OK 1
#endif

#define DI __device__ __forceinline__

__device__ int g_tc_ok;   // zero-initialized at module load

__global__ void probe_tc() {
#ifdef ETP_TC_OK
    g_tc_ok = 1;
#endif
}

// ======================= tcgen05 path constants ============================
namespace tc {
constexpr int BN  = 65536;
constexpr int TOK = 128;
constexpr int NT  = 256;
constexpr int NCTA = BN / TOK;          // 512

constexpr int OFF_MBAR = 64;            // 4 mbarriers
constexpr int OFF_W    = 1024;          // Wh: 3 chunks x 16384 ; Wl at +W_HL
constexpr int W_HL     = 49152;
constexpr int OFF_A    = OFF_W + 2 * W_HL;   // 99328
constexpr int A_HL     = 16384;
constexpr int A_BUF    = 32768;
constexpr int OFF_P0   = OFF_A + 2 * A_BUF;  // 164864
constexpr int P0S      = 129;
constexpr int SMEM_BYTES = OFF_P0 + TOK * P0S * 4;   // 230912

constexpr uint32_t IDESC =
    (1u << 4) | (1u << 7) | (1u << 10) | ((128u / 8) << 17) | ((128u / 16) << 24);

constexpr uint64_t DESC_BASE_SW128 =
    (uint64_t(2) << 61) | (uint64_t(1) << 46) | (uint64_t(64) << 32) | (uint64_t(1) << 16);
}

DI uint32_t smem_u32(const void* p) {
    uint32_t a;
    asm("{ .reg .u64 t; cvta.to.shared.u64 t, %1; cvt.u32.u64 %0, t; }" : "=r"(a) : "l"(p));
    return a;
}

#ifdef ETP_TC_OK
DI uint32_t elect_one() {
    uint32_t p;
    asm volatile("{ .reg .pred p; elect.sync _|p, 0xFFFFFFFF; selp.b32 %0,1,0,p; }" : "=r"(p));
    return p;
}
#define MBAR_INIT(a, n) \
    asm volatile("mbarrier.init.shared.b64 [%0], %1;" :: "r"(a), "r"(n) : "memory")
#define MBAR_WAIT(a, par) do {                                              \
    uint32_t _m = (a), _p = (par), _d;                                      \
    asm volatile("{ .reg .pred p; mbarrier.try_wait.parity.acquire.cta.shared::cta.b64 p, [%1], %2;" \
                 " selp.b32 %0,1,0,p; }" : "=r"(_d) : "r"(_m), "r"(_p) : "memory");          \
    if (!_d) asm volatile("{ .reg .pred P1; W%=:"                           \
        " mbarrier.try_wait.parity.acquire.cta.shared::cta.b64 P1, [%0], %1, 0x989680;" \
        " @P1 bra.uni D%=; bra.uni W%=; D%=: }" :: "r"(_m), "r"(_p) : "memory"); \
} while (0)
#define TC_ALLOC(sa, n)  asm volatile("tcgen05.alloc.cta_group::1.sync.aligned.shared::cta.b32 [%0], %1;" :: "r"(sa), "r"(n) : "memory")
#define TC_DEALLOC(t, n) asm volatile("tcgen05.dealloc.cta_group::1.sync.aligned.b32 %0, %1;" :: "r"(t), "r"(n))
#define TC_RELINQ()      asm volatile("tcgen05.relinquish_alloc_permit.cta_group::1.sync.aligned;")
#define TC_COMMIT(mb)    asm volatile("tcgen05.commit.cta_group::1.mbarrier::arrive::one.shared::cluster.b64 [%0];" :: "r"(mb) : "memory")
#define TC_WAIT_LD()     asm volatile("tcgen05.wait::ld.sync.aligned;" ::: "memory")
#define TC_FENCE_BEFORE() asm volatile("tcgen05.fence::before_thread_sync;" ::: "memory")
#define TC_FENCE_AFTER()  asm volatile("tcgen05.fence::after_thread_sync;" ::: "memory")
#define FENCE_ASYNC()     asm volatile("fence.proxy.async.shared::cta;" ::: "memory")

#define LD16(r, a) \
    asm volatile("tcgen05.ld.sync.aligned.32x32b.x16.b32 " \
        "{%0,%1,%2,%3,%4,%5,%6,%7,%8,%9,%10,%11,%12,%13,%14,%15}, [%16];" \
        : "=r"((r)[0]), "=r"((r)[1]), "=r"((r)[2]), "=r"((r)[3]),   \
          "=r"((r)[4]), "=r"((r)[5]), "=r"((r)[6]), "=r"((r)[7]),   \
          "=r"((r)[8]), "=r"((r)[9]), "=r"((r)[10]), "=r"((r)[11]), \
          "=r"((r)[12]), "=r"((r)[13]), "=r"((r)[14]), "=r"((r)[15]) \
        : "r"(a))

DI uint64_t mkdesc(uint32_t sa) {
    return tc::DESC_BASE_SW128 | (uint64_t(sa >> 4) & 0x3FFF);
}
DI void mma_ss(uint32_t d, uint64_t ad, uint64_t bd, uint32_t en) {
    asm volatile("{ .reg .pred p; setp.ne.u32 p, %4, 0;"
                 " tcgen05.mma.cta_group::1.kind::f16 [%0], %1, %2, %3, {%5,%5,%5,%5}, p; }"
                 :: "r"(d), "l"(ad), "l"(bd), "r"(tc::IDESC), "r"(en), "r"(0u) : "memory");
}
DI void issue_chunk(uint32_t d, uint32_t a, uint32_t w, bool first) {
    uint64_t ah = mkdesc(a), al = mkdesc(a + tc::A_HL);
    uint64_t wh = mkdesc(w), wl = mkdesc(w + tc::W_HL);
#pragma unroll
    for (int s = 0; s < 4; s++) {
        mma_ss(d, ah + 2 * s, wh + 2 * s, (first && s == 0) ? 0u : 1u);
        mma_ss(d, ah + 2 * s, wl + 2 * s, 1u);
        mma_ss(d, al + 2 * s, wh + 2 * s, 1u);
    }
}
DI void wait_commit(uint32_t mb, int idx) {
    MBAR_WAIT(mb + (idx & 3) * 8, (idx >> 2) & 1);
}

DI int swz(int off) { return off ^ ((off >> 3) & 0x70); }

DI void cvt_store(float x0, float x1, char* dh, char* dl, int so) {
    __nv_bfloat16 h0 = __float2bfloat16(x0), h1 = __float2bfloat16(x1);
    float r0 = x0 - __bfloat162float(h0), r1 = x1 - __bfloat162float(h1);
    __nv_bfloat16 l0 = __float2bfloat16(r0), l1 = __float2bfloat16(r1);
    uint32_t hp = (uint32_t)__bfloat16_as_ushort(h0) | ((uint32_t)__bfloat16_as_ushort(h1) << 16);
    uint32_t lp = (uint32_t)__bfloat16_as_ushort(l0) | ((uint32_t)__bfloat16_as_ushort(l1) << 16);
    *(uint32_t*)(dh + so) = hp;
    *(uint32_t*)(dl + so) = lp;
}

template <int ROWS>
DI void conv_block(const float* __restrict__ g, int gs, char* dh, char* dl) {
    for (int idx = threadIdx.x; idx < ROWS * 32; idx += tc::NT) {
        int row = idx >> 5, kp = idx & 31;
        float2 v = *reinterpret_cast<const float2*>(g + (long long)row * gs + kp * 2);
        cvt_store(v.x, v.y, dh, dl, swz(row * 128 + kp * 4));
    }
}
#endif  // ETP_TC_OK

__global__ __launch_bounds__(tc::NT, 1) __cluster_dims__(1, 1, 1)
void etp_tc(const float* __restrict__ z0,  const float* __restrict__ z1,
            const float* __restrict__ W0l, const float* __restrict__ b0l,
            const float* __restrict__ W0r, const float* __restrict__ b0r,
            const float* __restrict__ W1l, const float* __restrict__ W1r,
            const float* __restrict__ W0o, const float* __restrict__ b0o,
            const float* __restrict__ W1o, float* __restrict__ out) {
#ifdef ETP_TC_OK
    using namespace tc;
    extern __shared__ char sm[];
    const uint32_t smb = smem_u32(sm);
    const int tid = threadIdx.x, wid = tid >> 5, lane = tid & 31;
    const int t0 = blockIdx.x * TOK;

    char* sWh = sm + OFF_W;
    char* sA0 = sm + OFF_A;
    char* sA1 = sA0 + A_BUF;
    float* sP0 = reinterpret_cast<float*>(sm + OFF_P0);
    const uint32_t mb = smb + OFF_MBAR;
    const uint32_t uW = smb + OFF_W, uA0 = smb + OFF_A, uA1 = uA0 + A_BUF;
    float* out0 = out;
    float* out1 = out + (size_t)BN * 128;

    if (tid == 0)
        for (int s = 0; s < 4; s++) MBAR_INIT(mb + 8 * s, 1);
    if (wid == 0) TC_ALLOC(smb, 512);
    __syncthreads();
    uint32_t tb;
    asm volatile("ld.shared.b32 %0, [%1];" : "=r"(tb) : "r"(smb));

    const uint32_t woff = (uint32_t)(wid & 3) << 21;
    const int half = wid >> 2;
    const int tok = 32 * (wid & 3) + lane;

    // ======== Phase 1: GEMM1 (P0 -> cols 0-127) ========
    conv_block<64>(W0l,      128, sWh,                      sWh + W_HL);
    conv_block<64>(W0l + 64, 128, sWh + 16384,              sWh + W_HL + 16384);
    conv_block<64>(W0r,      128, sWh + 64 * 128,           sWh + W_HL + 64 * 128);
    conv_block<64>(W0r + 64, 128, sWh + 16384 + 64 * 128,   sWh + W_HL + 16384 + 64 * 128);
    conv_block<128>(z0 + (size_t)t0 * 128, 128, sA0, sA0 + A_HL);
    FENCE_ASYNC();
    __syncthreads();
    if (wid == 0 && elect_one()) { issue_chunk(tb, uA0, uW, true);  TC_COMMIT(mb + 0); }   // id0
    conv_block<128>(z0 + (size_t)t0 * 128 + 64, 128, sA1, sA1 + A_HL);
    FENCE_ASYNC();
    __syncthreads();
    if (wid == 0 && elect_one()) { issue_chunk(tb, uA1, uW + 16384, false); TC_COMMIT(mb + 8); } // id1

    // ---- P0 drain (+bias) to SMEM; convert W1l/W1r ----
    wait_commit(mb, 1);
    TC_FENCE_AFTER();
    for (int ch = 0; ch < 4; ch++) {
        int c0 = 64 * half + 16 * ch;
        uint32_t r[16];
        LD16(r, tb + c0 + woff);
        TC_WAIT_LD();
#pragma unroll
        for (int j = 0; j < 16; j++) {
            int n = c0 + j;
            float b = (n < 64) ? b0l[n] : b0r[n - 64];
            sP0[tok * P0S + n] = __uint_as_float(r[j]) + b;
        }
    }
    conv_block<64>(W1l,      128, sWh,                      sWh + W_HL);
    conv_block<64>(W1l + 64, 128, sWh + 16384,              sWh + W_HL + 16384);
    conv_block<64>(W1r,      128, sWh + 64 * 128,           sWh + W_HL + 64 * 128);
    conv_block<64>(W1r + 64, 128, sWh + 16384 + 64 * 128,   sWh + W_HL + 16384 + 64 * 128);
    TC_FENCE_BEFORE();
    FENCE_ASYNC();
    __syncthreads();

    // ======== Phase 2: GEMM2 (P1_i -> cols 128+128i) ========
    for (int i = 0; i < 3; i++)
#pragma unroll 1
        for (int c = 0; c < 2; c++) {
            int cc = 2 * i + c;
            char* ab = (cc & 1) ? sA1 : sA0;
            uint32_t ua = (cc & 1) ? uA1 : uA0;
            if (cc >= 2) wait_commit(mb, cc);   // previous user of this buffer
            conv_block<128>(z1 + (size_t)t0 * 384 + i * 128 + 64 * c, 384, ab, ab + A_HL);
            FENCE_ASYNC();
            __syncthreads();
            if (wid == 0 && elect_one()) {
                issue_chunk(tb + 128 + 128 * i, ua, uW + 16384 * c, c == 0);
                TC_COMMIT(mb + 8 * ((2 + cc) & 3));                       // id 2+cc
            }
        }

    // ======== Phase 3: Y0 + GEMM3 + out0 ========
    wait_commit(mb, 7);
    TC_FENCE_AFTER();
    {
        const float* p0r = sP0 + tok * P0S;
        for (int ch = 0; ch < 2; ch++) {
            int r0 = 32 * half + 16 * ch;
            float s[16];
#pragma unroll
            for (int j = 0; j < 16; j++) s[j] = 0.f;
#pragma unroll
            for (int i = 0; i < 3; i++) {
                uint32_t lv[16], rv[16];
                LD16(lv, tb + 128 + 128 * i + r0 + woff);
                LD16(rv, tb + 128 + 128 * i + 64 + r0 + woff);
                TC_WAIT_LD();
#pragma unroll
                for (int j = 0; j < 16; j++)
                    s[j] += __uint_as_float(lv[j]) * __uint_as_float(rv[j]);
            }
#pragma unroll
            for (int j = 0; j < 16; j += 2) {
                int k = r0 + j;
                float a0 = p0r[k] * p0r[64 + k];
                float a1 = p0r[k + 1] * p0r[64 + k + 1];
                cvt_store(a0, a1, sA0, sA0 + A_HL, swz(tok * 128 + 2 * k));
                cvt_store(s[j], s[j + 1], sA1, sA1 + A_HL, swz(tok * 128 + 2 * k));
            }
        }
    }
    conv_block<128>(W0o,      128, sWh,         sWh + W_HL);
    conv_block<128>(W0o + 64, 128, sWh + 16384, sWh + W_HL + 16384);
    TC_FENCE_BEFORE();
    FENCE_ASYNC();
    __syncthreads();
    if (wid == 0 && elect_one()) {
        issue_chunk(tb, uA0, uW, true);
        issue_chunk(tb, uA1, uW + 16384, false);
        TC_COMMIT(mb + 0);                                                // id8
    }
    wait_commit(mb, 8);
    TC_FENCE_AFTER();
    for (int ch = 0; ch < 4; ch++) {
        int c0 = 64 * half + 16 * ch;
        uint32_t r[16];
        LD16(r, tb + c0 + woff);
        TC_WAIT_LD();
#pragma unroll
        for (int j4 = 0; j4 < 4; j4++) {
            float4 v;
            v.x = __uint_as_float(r[4 * j4 + 0]) + b0o[c0 + 4 * j4 + 0];
            v.y = __uint_as_float(r[4 * j4 + 1]) + b0o[c0 + 4 * j4 + 1];
            v.z = __uint_as_float(r[4 * j4 + 2]) + b0o[c0 + 4 * j4 + 2];
            v.w = __uint_as_float(r[4 * j4 + 3]) + b0o[c0 + 4 * j4 + 3];
            *reinterpret_cast<float4*>(out0 + (size_t)(t0 + tok) * 128 + c0 + 4 * j4) = v;
        }
    }
    conv_block<128>(W1o,       192, sWh,             sWh + W_HL);
    conv_block<128>(W1o + 64,  192, sWh + 16384,     sWh + W_HL + 16384);
    conv_block<128>(W1o + 128, 192, sWh + 2 * 16384, sWh + W_HL + 2 * 16384);
    TC_FENCE_BEFORE();
    FENCE_ASYNC();
    __syncthreads();

    // ======== Phase 4: per component: Y1_i + GEMM4_i + out1_i ========
#pragma unroll 1
    for (int i = 0; i < 3; i++) {
        const int i1 = (i + 1 == 3) ? 0 : i + 1;
        const int i2 = (i + 2 >= 3) ? i - 1 : i + 2;
        const float* p0r = sP0 + tok * P0S;
#pragma unroll 1
        for (int c = 0; c < 3; c++) {
            int cc = 3 * i + c;
            char* ab = (cc & 1) ? sA1 : sA0;
            uint32_t ua = (cc & 1) ? uA1 : uA0;
            if (cc >= 2) wait_commit(mb, 9 + cc - 2);
            for (int ch = 0; ch < 2; ch++) {
                int r0 = 32 * half + 16 * ch;
                if (c == 0) {                 // q011 = z0_l * z1_r[i]
                    uint32_t rv[16];
                    LD16(rv, tb + 128 + 128 * i + 64 + r0 + woff);
                    TC_WAIT_LD();
#pragma unroll
                    for (int j = 0; j < 16; j += 2) {
                        int k = r0 + j;
                        float y0 = p0r[k]     * __uint_as_float(rv[j]);
                        float y1 = p0r[k + 1] * __uint_as_float(rv[j + 1]);
                        cvt_store(y0, y1, ab, ab + A_HL, swz(tok * 128 + 2 * k));
                    }
                } else if (c == 1) {          // q101 = z1_l[i] * z0_r
                    uint32_t lv[16];
                    LD16(lv, tb + 128 + 128 * i + r0 + woff);
                    TC_WAIT_LD();
#pragma unroll
                    for (int j = 0; j < 16; j += 2) {
                        int k = r0 + j;
                        float y0 = __uint_as_float(lv[j])     * p0r[64 + k];
                        float y1 = __uint_as_float(lv[j + 1]) * p0r[64 + k + 1];
                        cvt_store(y0, y1, ab, ab + A_HL, swz(tok * 128 + 2 * k));
                    }
                } else {                      // q111 = l_i1*r_i2 - l_i2*r_i1
                    uint32_t va[16], vb[16], vc[16], vd[16];
                    LD16(va, tb + 128 + 128 * i1 + r0 + woff);
                    LD16(vb, tb + 128 + 128 * i2 + 64 + r0 + woff);
                    LD16(vc, tb + 128 + 128 * i2 + r0 + woff);
                    LD16(vd, tb + 128 + 128 * i1 + 64 + r0 + woff);
                    TC_WAIT_LD();
#pragma unroll
                    for (int j = 0; j < 16; j += 2) {
                        int k = r0 + j;
                        float y0 = __uint_as_float(va[j]) * __uint_as_float(vb[j])
                                 - __uint_as_float(vc[j]) * __uint_as_float(vd[j]);
                        float y1 = __uint_as_float(va[j + 1]) * __uint_as_float(vb[j + 1])
                                 - __uint_as_float(vc[j + 1]) * __uint_as_float(vd[j + 1]);
                        cvt_store(y0, y1, ab, ab + A_HL, swz(tok * 128 + 2 * k));
                    }
                }
            }
            FENCE_ASYNC();
            __syncthreads();
            if (wid == 0 && elect_one()) {
                issue_chunk(tb, ua, uW + 16384 * c, c == 0);
                TC_COMMIT(mb + 8 * ((9 + cc) & 3));                       // id 9+cc
            }
        }
        wait_commit(mb, 9 + 3 * i + 2);
        TC_FENCE_AFTER();
        for (int ch = 0; ch < 4; ch++) {
            int c0 = 64 * half + 16 * ch;
            uint32_t r[16];
            LD16(r, tb + c0 + woff);
            TC_WAIT_LD();
#pragma unroll
            for (int j4 = 0; j4 < 4; j4++) {
                float4 v;
                v.x = __uint_as_float(r[4 * j4 + 0]);
                v.y = __uint_as_float(r[4 * j4 + 1]);
                v.z = __uint_as_float(r[4 * j4 + 2]);
                v.w = __uint_as_float(r[4 * j4 + 3]);
                *reinterpret_cast<float4*>(out1 + (size_t)(t0 + tok) * 384 + i * 128 + c0 + 4 * j4) = v;
            }
        }
        TC_FENCE_BEFORE();
        __syncthreads();
    }

    __syncthreads();
    if (wid == 0) {
        TC_RELINQ();
        TC_DEALLOC(tb, 512);
    }
#endif  // ETP_TC_OK
}

// ======================= FFMA2 fallback (round-1) ==========================
namespace fb {
constexpr int BN   = 65536;
constexpr int TOK  = 32;
constexpr int NT   = 256;
constexpr int P128 = 132;
constexpr int P192 = 196;
constexpr int SW_F  = 128 * P192;
constexpr int SB_F  = 96 * P128;
constexpr int SP0_F = TOK * P128;
constexpr int SP1_F = 96 * P128;
constexpr int SMEM_F = SW_F + SB_F + SP0_F + SP1_F;
constexpr int SMEM_BYTES = SMEM_F * 4;   // 218624
}

using ull = unsigned long long;

DI void ffma2(ull& d, ull a, ull b) {
    asm volatile("fma.rn.f32x2 %0, %1, %2, %0;" : "+l"(d) : "l"(a), "l"(b));
}
DI float hsum2(ull v) {
    float lo, hi;
    asm("mov.b64 {%0, %1}, %2;" : "=f"(lo), "=f"(hi) : "l"(v));
    return lo + hi;
}

template<int ROWS, int COLS, int PADV>
DI void fb_copy_tile(const float* __restrict__ g, float* __restrict__ s) {
    constexpr int N4 = ROWS * COLS / 4;
    constexpr int C4 = COLS / 4;
    for (int idx = threadIdx.x; idx < N4; idx += fb::NT) {
        int r = idx / C4;
        int c = idx - r * C4;
        float4 v = *reinterpret_cast<const float4*>(g + (long long)r * COLS + c * 4);
        *reinterpret_cast<float4*>(s + r * PADV + c * 4) = v;
    }
}

template<int K, int PADA, int PADW, int TM, int TN, int NOG>
DI void gemm_core(const float* __restrict__ A, const float* __restrict__ W,
                  int m0, int og, float (&res)[TM][TN]) {
    ull acc[TM][TN];
#pragma unroll
    for (int i = 0; i < TM; i++)
#pragma unroll
        for (int j = 0; j < TN; j++) acc[i][j] = 0ull;
#pragma unroll 4
    for (int k4 = 0; k4 < K / 4; k4++) {
        ulonglong2 a[TM], b[TN];
#pragma unroll
        for (int i = 0; i < TM; i++)
            a[i] = *reinterpret_cast<const ulonglong2*>(A + (m0 + i) * PADA + k4 * 4);
#pragma unroll
        for (int j = 0; j < TN; j++)
            b[j] = *reinterpret_cast<const ulonglong2*>(W + (og + j * NOG) * PADW + k4 * 4);
#pragma unroll
        for (int i = 0; i < TM; i++)
#pragma unroll
            for (int j = 0; j < TN; j++) {
                ffma2(acc[i][j], a[i].x, b[j].x);
                ffma2(acc[i][j], a[i].y, b[j].y);
            }
    }
#pragma unroll
    for (int i = 0; i < TM; i++)
#pragma unroll
        for (int j = 0; j < TN; j++) res[i][j] = hsum2(acc[i][j]);
}

__global__ __launch_bounds__(fb::NT, 1)
void etp_fb(const float* __restrict__ z0,  const float* __restrict__ z1,
            const float* __restrict__ W0l, const float* __restrict__ b0l,
            const float* __restrict__ W0r, const float* __restrict__ b0r,
            const float* __restrict__ W1l, const float* __restrict__ W1r,
            const float* __restrict__ W0o, const float* __restrict__ b0o,
            const float* __restrict__ W1o, float* __restrict__ out) {
    using namespace fb;
    if (g_tc_ok) return;   // tensor-core path handled the work

    extern __shared__ float smf[];
    float* sW  = smf;
    float* sB  = sW + SW_F;
    float* sP0 = sB + SB_F;
    float* sP1 = sP0 + SP0_F;

    const int tid = threadIdx.x;
    const int t0  = blockIdx.x * TOK;
    float* out0 = out;
    float* out1 = out + (long long)BN * 128;

    fb_copy_tile<64, 128, P128>(W0l, sW);
    fb_copy_tile<64, 128, P128>(W0r, sW + 64 * P128);
    fb_copy_tile<TOK, 128, P128>(z0 + (long long)t0 * 128, sB);
    __syncthreads();
    {
        const int og = tid & 31, tg = tid >> 5, m0 = tg * 4;
        float rv[4][4];
        gemm_core<128, P128, P128, 4, 4, 32>(sB, sW, m0, og, rv);
#pragma unroll
        for (int i = 0; i < 4; i++)
#pragma unroll
            for (int j = 0; j < 4; j++) {
                int n = og + j * 32;
                float bias = (n < 64) ? b0l[n] : b0r[n - 64];
                sP0[(m0 + i) * P128 + n] = rv[i][j] + bias;
            }
    }
    __syncthreads();

    fb_copy_tile<64, 128, P128>(W1l, sW);
    fb_copy_tile<64, 128, P128>(W1r, sW + 64 * P128);
    fb_copy_tile<96, 128, P128>(z1 + (long long)t0 * 3 * 128, sB);
    __syncthreads();
    {
        const int og = tid & 15, tg = tid >> 4, m0 = tg * 6;
        float rv[6][8];
        gemm_core<128, P128, P128, 6, 8, 16>(sB, sW, m0, og, rv);
#pragma unroll
        for (int i = 0; i < 6; i++)
#pragma unroll
            for (int j = 0; j < 8; j++)
                sP1[(m0 + i) * P128 + og + j * 16] = rv[i][j];
    }
    __syncthreads();

    for (int idx = tid; idx < TOK * 64; idx += NT) {
        int t = idx >> 6, r = idx & 63;
        const float* p0 = sP0 + t * P128;
        const float* p1 = sP1 + 3 * t * P128;
        sB[t * P128 + r] = p0[r] * p0[64 + r];
        float s = p1[r]            * p1[64 + r]
                + p1[P128 + r]     * p1[P128 + 64 + r]
                + p1[2 * P128 + r] * p1[2 * P128 + 64 + r];
        sB[t * P128 + 64 + r] = s;
    }
    fb_copy_tile<128, 128, P128>(W0o, sW);
    __syncthreads();

    {
        const int og = tid & 31, tg = tid >> 5, m0 = tg * 4;
        float rv[4][4];
        gemm_core<128, P128, P128, 4, 4, 32>(sB, sW, m0, og, rv);
#pragma unroll
        for (int i = 0; i < 4; i++)
#pragma unroll
            for (int j = 0; j < 4; j++) {
                int n = og + j * 32;
                out0[(long long)(t0 + m0 + i) * 128 + n] = rv[i][j] + b0o[n];
            }
    }
    __syncthreads();

    fb_copy_tile<128, 192, P192>(W1o, sW);

#pragma unroll 1
    for (int ic = 0; ic < 3; ic++) {
        const int i1 = (ic + 1) == 3 ? 0 : ic + 1;
        const int i2 = (ic + 2) >= 3 ? ic - 1 : ic + 2;
        for (int idx = tid; idx < TOK * 64; idx += NT) {
            int t = idx >> 6, r = idx & 63;
            const float* p0 = sP0 + t * P128;
            const float* p1 = sP1 + 3 * t * P128;
            float q011 = p0[r] * p1[ic * P128 + 64 + r];
            float q101 = p1[ic * P128 + r] * p0[64 + r];
            float q111 = p1[i1 * P128 + r] * p1[i2 * P128 + 64 + r]
                       - p1[i2 * P128 + r] * p1[i1 * P128 + 64 + r];
            float* y = sB + t * P192;
            y[r]       = q011;
            y[64 + r]  = q101;
            y[128 + r] = q111;
        }
        __syncthreads();
        {
            const int og = tid & 31, tg = tid >> 5, m0 = tg * 4;
            float rv[4][4];
            gemm_core<192, P192, P192, 4, 4, 32>(sB, sW, m0, og, rv);
#pragma unroll
            for (int i = 0; i < 4; i++)
#pragma unroll
                for (int j = 0; j < 4; j++) {
                    int n = og + j * 32;
                    out1[(long long)(t0 + m0 + i) * 384 + ic * 128 + n] = rv[i][j];
                }
        }
        __syncthreads();
    }
}

// ============================== launcher ===================================
extern "C" void kernel_launch(void* const* d_in, const int* in_sizes, int n_in,
                              void* d_out, int out_size) {
    (void)in_sizes; (void)n_in; (void)out_size;
    cudaFuncSetAttribute(etp_tc, cudaFuncAttributeMaxDynamicSharedMemorySize,
                         tc::SMEM_BYTES);
    cudaFuncSetAttribute(etp_fb, cudaFuncAttributeMaxDynamicSharedMemorySize,
                         fb::SMEM_BYTES);

    const float* z0  = (const float*)d_in[0];
    const float* z1  = (const float*)d_in[1];
    const float* W0l = (const float*)d_in[2];
    const float* b0l = (const float*)d_in[3];
    const float* W0r = (const float*)d_in[4];
    const float* b0r = (const float*)d_in[5];
    const float* W1l = (const float*)d_in[6];
    const float* W1r = (const float*)d_in[7];
    const float* W0o = (const float*)d_in[8];
    const float* b0o = (const float*)d_in[9];
    const float* W1o = (const float*)d_in[10];
    float* outp = (float*)d_out;

    probe_tc<<<1, 1>>>();
    etp_tc<<<tc::NCTA, tc::NT, tc::SMEM_BYTES>>>(z0, z1, W0l, b0l, W0r, b0r,
                                                 W1l, W1r, W0o, b0o, W1o, outp);
    etp_fb<<<fb::BN / fb::TOK, fb::NT, fb::SMEM_BYTES>>>(z0, z1, W0l, b0l, W0r, b0r,
                                                         W1l, W1r, W0o, b0o, W1o, outp);
}

// round 4
// speedup vs baseline: 3.2533x; 1.9471x over previous
#include <cuda_runtime.h>
#include <cuda_bf16.h>
#include <cstdint>

// ===========================================================================
// ElementwiseTensorProducts on tcgen05 (sm_103a), bf16 hi/lo split (3-pass).
// R4: fully-unrolled converts (MLP fix), GMEM loads pipelined across mbarrier
// waits, single launch (fallback removed — tc path proven live in R3).
// ===========================================================================

#if defined(__CUDA_ARCH_FEAT_SM103_ALL) || defined(__CUDA_ARCH_FEAT_SM100_ALL) || \
    defined(__CUDA_ARCH_FEAT_SM101_ALL) || defined(__CUDA_ARCH_SPECIFIC__) ||     \
    defined(__CUDA_ARCH_FAMILY_SPECIFIC__)
#define ETP_TC_OK 1
#endif

#define DI __device__ __forceinline__

namespace tc {
constexpr int BN  = 65536;
constexpr int TOK = 128;
constexpr int NT  = 256;
constexpr int NCTA = BN / TOK;          // 512

constexpr int OFF_MBAR = 64;            // 4 mbarriers
constexpr int OFF_W    = 1024;          // Wh: 3 chunks x 16384 ; Wl at +W_HL
constexpr int W_HL     = 49152;
constexpr int OFF_A    = OFF_W + 2 * W_HL;   // 99328
constexpr int A_HL     = 16384;
constexpr int A_BUF    = 32768;
constexpr int OFF_P0   = OFF_A + 2 * A_BUF;  // 164864
constexpr int P0S      = 129;
constexpr int SMEM_BYTES = OFF_P0 + TOK * P0S * 4;   // 230912

constexpr uint32_t IDESC =
    (1u << 4) | (1u << 7) | (1u << 10) | ((128u / 8) << 17) | ((128u / 16) << 24);

constexpr uint64_t DESC_BASE_SW128 =
    (uint64_t(2) << 61) | (uint64_t(1) << 46) | (uint64_t(64) << 32) | (uint64_t(1) << 16);
}

DI uint32_t smem_u32(const void* p) {
    uint32_t a;
    asm("{ .reg .u64 t; cvta.to.shared.u64 t, %1; cvt.u32.u64 %0, t; }" : "=r"(a) : "l"(p));
    return a;
}

#ifdef ETP_TC_OK
DI uint32_t elect_one() {
    uint32_t p;
    asm volatile("{ .reg .pred p; elect.sync _|p, 0xFFFFFFFF; selp.b32 %0,1,0,p; }" : "=r"(p));
    return p;
}
#define MBAR_INIT(a, n) \
    asm volatile("mbarrier.init.shared.b64 [%0], %1;" :: "r"(a), "r"(n) : "memory")
#define MBAR_WAIT(a, par) do {                                              \
    uint32_t _m = (a), _p = (par), _d;                                      \
    asm volatile("{ .reg .pred p; mbarrier.try_wait.parity.acquire.cta.shared::cta.b64 p, [%1], %2;" \
                 " selp.b32 %0,1,0,p; }" : "=r"(_d) : "r"(_m), "r"(_p) : "memory");          \
    if (!_d) asm volatile("{ .reg .pred P1; W%=:"                           \
        " mbarrier.try_wait.parity.acquire.cta.shared::cta.b64 P1, [%0], %1, 0x989680;" \
        " @P1 bra.uni D%=; bra.uni W%=; D%=: }" :: "r"(_m), "r"(_p) : "memory"); \
} while (0)
#define TC_ALLOC(sa, n)  asm volatile("tcgen05.alloc.cta_group::1.sync.aligned.shared::cta.b32 [%0], %1;" :: "r"(sa), "r"(n) : "memory")
#define TC_DEALLOC(t, n) asm volatile("tcgen05.dealloc.cta_group::1.sync.aligned.b32 %0, %1;" :: "r"(t), "r"(n))
#define TC_RELINQ()      asm volatile("tcgen05.relinquish_alloc_permit.cta_group::1.sync.aligned;")
#define TC_COMMIT(mb)    asm volatile("tcgen05.commit.cta_group::1.mbarrier::arrive::one.shared::cluster.b64 [%0];" :: "r"(mb) : "memory")
#define TC_WAIT_LD()     asm volatile("tcgen05.wait::ld.sync.aligned;" ::: "memory")
#define TC_FENCE_BEFORE() asm volatile("tcgen05.fence::before_thread_sync;" ::: "memory")
#define TC_FENCE_AFTER()  asm volatile("tcgen05.fence::after_thread_sync;" ::: "memory")
#define FENCE_ASYNC()     asm volatile("fence.proxy.async.shared::cta;" ::: "memory")

#define LD16(r, a) \
    asm volatile("tcgen05.ld.sync.aligned.32x32b.x16.b32 " \
        "{%0,%1,%2,%3,%4,%5,%6,%7,%8,%9,%10,%11,%12,%13,%14,%15}, [%16];" \
        : "=r"((r)[0]), "=r"((r)[1]), "=r"((r)[2]), "=r"((r)[3]),   \
          "=r"((r)[4]), "=r"((r)[5]), "=r"((r)[6]), "=r"((r)[7]),   \
          "=r"((r)[8]), "=r"((r)[9]), "=r"((r)[10]), "=r"((r)[11]), \
          "=r"((r)[12]), "=r"((r)[13]), "=r"((r)[14]), "=r"((r)[15]) \
        : "r"(a))

DI uint64_t mkdesc(uint32_t sa) {
    return tc::DESC_BASE_SW128 | (uint64_t(sa >> 4) & 0x3FFF);
}
DI void mma_ss(uint32_t d, uint64_t ad, uint64_t bd, uint32_t en) {
    asm volatile("{ .reg .pred p; setp.ne.u32 p, %4, 0;"
                 " tcgen05.mma.cta_group::1.kind::f16 [%0], %1, %2, %3, {%5,%5,%5,%5}, p; }"
                 :: "r"(d), "l"(ad), "l"(bd), "r"(tc::IDESC), "r"(en), "r"(0u) : "memory");
}
DI void issue_chunk(uint32_t d, uint32_t a, uint32_t w, bool first) {
    uint64_t ah = mkdesc(a), al = mkdesc(a + tc::A_HL);
    uint64_t wh = mkdesc(w), wl = mkdesc(w + tc::W_HL);
#pragma unroll
    for (int s = 0; s < 4; s++) {
        mma_ss(d, ah + 2 * s, wh + 2 * s, (first && s == 0) ? 0u : 1u);
        mma_ss(d, ah + 2 * s, wl + 2 * s, 1u);
        mma_ss(d, al + 2 * s, wh + 2 * s, 1u);
    }
}
DI void wait_commit(uint32_t mb, int idx) {
    MBAR_WAIT(mb + (idx & 3) * 8, (idx >> 2) & 1);
}

DI int swz(int off) { return off ^ ((off >> 3) & 0x70); }

DI void cvt_store(float x0, float x1, char* dh, char* dl, int so) {
    __nv_bfloat16 h0 = __float2bfloat16(x0), h1 = __float2bfloat16(x1);
    float r0 = x0 - __bfloat162float(h0), r1 = x1 - __bfloat162float(h1);
    __nv_bfloat16 l0 = __float2bfloat16(r0), l1 = __float2bfloat16(r1);
    uint32_t hp = (uint32_t)__bfloat16_as_ushort(h0) | ((uint32_t)__bfloat16_as_ushort(h1) << 16);
    uint32_t lp = (uint32_t)__bfloat16_as_ushort(l0) | ((uint32_t)__bfloat16_as_ushort(l1) << 16);
    *(uint32_t*)(dh + so) = hp;
    *(uint32_t*)(dl + so) = lp;
}

// ---- fully unrolled load/store halves (max MLP) ----
template <int ROWS>
DI void ld_regs(const float* __restrict__ g, int gs, float2 (&v)[ROWS * 32 / tc::NT]) {
    constexpr int IT = ROWS * 32 / tc::NT;
#pragma unroll
    for (int it = 0; it < IT; it++) {
        int idx = threadIdx.x + it * tc::NT;
        int row = idx >> 5, kp = idx & 31;
        v[it] = *reinterpret_cast<const float2*>(g + (long long)row * gs + kp * 2);
    }
}
template <int ROWS>
DI void st_regs(const float2 (&v)[ROWS * 32 / tc::NT], char* dh, char* dl) {
    constexpr int IT = ROWS * 32 / tc::NT;
#pragma unroll
    for (int it = 0; it < IT; it++) {
        int idx = threadIdx.x + it * tc::NT;
        int row = idx >> 5, kp = idx & 31;
        cvt_store(v[it].x, v[it].y, dh, dl, swz(row * 128 + kp * 4));
    }
}
template <int ROWS>
DI void conv_block(const float* __restrict__ g, int gs, char* dh, char* dl) {
    float2 v[ROWS * 32 / tc::NT];
    ld_regs<ROWS>(g, gs, v);
    st_regs<ROWS>(v, dh, dl);
}
#endif  // ETP_TC_OK

__global__ __launch_bounds__(tc::NT, 1) __cluster_dims__(1, 1, 1)
void etp_tc(const float* __restrict__ z0,  const float* __restrict__ z1,
            const float* __restrict__ W0l, const float* __restrict__ b0l,
            const float* __restrict__ W0r, const float* __restrict__ b0r,
            const float* __restrict__ W1l, const float* __restrict__ W1r,
            const float* __restrict__ W0o, const float* __restrict__ b0o,
            const float* __restrict__ W1o, float* __restrict__ out) {
#ifdef ETP_TC_OK
    using namespace tc;
    extern __shared__ char sm[];
    const uint32_t smb = smem_u32(sm);
    const int tid = threadIdx.x, wid = tid >> 5, lane = tid & 31;
    const int t0 = blockIdx.x * TOK;

    char* sWh = sm + OFF_W;
    char* sA0 = sm + OFF_A;
    char* sA1 = sA0 + A_BUF;
    float* sP0 = reinterpret_cast<float*>(sm + OFF_P0);
    const uint32_t mb = smb + OFF_MBAR;
    const uint32_t uW = smb + OFF_W, uA0 = smb + OFF_A, uA1 = uA0 + A_BUF;
    float* out0 = out;
    float* out1 = out + (size_t)BN * 128;

    if (tid == 0)
        for (int s = 0; s < 4; s++) MBAR_INIT(mb + 8 * s, 1);
    if (wid == 0) TC_ALLOC(smb, 512);
    __syncthreads();
    uint32_t tb;
    asm volatile("ld.shared.b32 %0, [%1];" : "=r"(tb) : "r"(smb));

    const uint32_t woff = (uint32_t)(wid & 3) << 21;
    const int half = wid >> 2;
    const int tok = 32 * (wid & 3) + lane;

    // ======== Phase 1: GEMM1 (P0 -> cols 0-127) ========
    conv_block<64>(W0l,      128, sWh,                      sWh + W_HL);
    conv_block<64>(W0l + 64, 128, sWh + 16384,              sWh + W_HL + 16384);
    conv_block<64>(W0r,      128, sWh + 64 * 128,           sWh + W_HL + 64 * 128);
    conv_block<64>(W0r + 64, 128, sWh + 16384 + 64 * 128,   sWh + W_HL + 16384 + 64 * 128);
    conv_block<128>(z0 + (size_t)t0 * 128, 128, sA0, sA0 + A_HL);
    FENCE_ASYNC();
    __syncthreads();
    if (wid == 0 && elect_one()) { issue_chunk(tb, uA0, uW, true);  TC_COMMIT(mb + 0); }   // id0
    conv_block<128>(z0 + (size_t)t0 * 128 + 64, 128, sA1, sA1 + A_HL);
    FENCE_ASYNC();
    __syncthreads();
    if (wid == 0 && elect_one()) { issue_chunk(tb, uA1, uW + 16384, false); TC_COMMIT(mb + 8); } // id1

    // ---- P0 drain (+bias) to SMEM; convert W1l/W1r ----
    wait_commit(mb, 1);
    TC_FENCE_AFTER();
    for (int ch = 0; ch < 4; ch++) {
        int c0 = 64 * half + 16 * ch;
        uint32_t r[16];
        LD16(r, tb + c0 + woff);
        TC_WAIT_LD();
#pragma unroll
        for (int j = 0; j < 16; j++) {
            int n = c0 + j;
            float b = (n < 64) ? b0l[n] : b0r[n - 64];
            sP0[tok * P0S + n] = __uint_as_float(r[j]) + b;
        }
    }
    conv_block<64>(W1l,      128, sWh,                      sWh + W_HL);
    conv_block<64>(W1l + 64, 128, sWh + 16384,              sWh + W_HL + 16384);
    conv_block<64>(W1r,      128, sWh + 64 * 128,           sWh + W_HL + 64 * 128);
    conv_block<64>(W1r + 64, 128, sWh + 16384 + 64 * 128,   sWh + W_HL + 16384 + 64 * 128);
    TC_FENCE_BEFORE();
    FENCE_ASYNC();
    __syncthreads();

    // ======== Phase 2: GEMM2 (P1_i -> cols 128+128i) ========
    for (int i = 0; i < 3; i++)
#pragma unroll 1
        for (int c = 0; c < 2; c++) {
            int cc = 2 * i + c;
            char* ab = (cc & 1) ? sA1 : sA0;
            uint32_t ua = (cc & 1) ? uA1 : uA0;
            float2 v[16];
            ld_regs<128>(z1 + (size_t)t0 * 384 + i * 128 + 64 * c, 384, v);  // loads in flight
            if (cc >= 2) wait_commit(mb, cc);   // previous user of this buffer
            st_regs<128>(v, ab, ab + A_HL);
            FENCE_ASYNC();
            __syncthreads();
            if (wid == 0 && elect_one()) {
                issue_chunk(tb + 128 + 128 * i, ua, uW + 16384 * c, c == 0);
                TC_COMMIT(mb + 8 * ((2 + cc) & 3));                       // id 2+cc
            }
        }

    // ======== Phase 3: Y0 + GEMM3 + out0 ========
    wait_commit(mb, 7);
    TC_FENCE_AFTER();
    {
        const float* p0r = sP0 + tok * P0S;
        for (int ch = 0; ch < 2; ch++) {
            int r0 = 32 * half + 16 * ch;
            float s[16];
#pragma unroll
            for (int j = 0; j < 16; j++) s[j] = 0.f;
#pragma unroll
            for (int i = 0; i < 3; i++) {
                uint32_t lv[16], rv[16];
                LD16(lv, tb + 128 + 128 * i + r0 + woff);
                LD16(rv, tb + 128 + 128 * i + 64 + r0 + woff);
                TC_WAIT_LD();
#pragma unroll
                for (int j = 0; j < 16; j++)
                    s[j] += __uint_as_float(lv[j]) * __uint_as_float(rv[j]);
            }
#pragma unroll
            for (int j = 0; j < 16; j += 2) {
                int k = r0 + j;
                float a0 = p0r[k] * p0r[64 + k];
                float a1 = p0r[k + 1] * p0r[64 + k + 1];
                cvt_store(a0, a1, sA0, sA0 + A_HL, swz(tok * 128 + 2 * k));
                cvt_store(s[j], s[j + 1], sA1, sA1 + A_HL, swz(tok * 128 + 2 * k));
            }
        }
    }
    conv_block<128>(W0o,      128, sWh,         sWh + W_HL);
    conv_block<128>(W0o + 64, 128, sWh + 16384, sWh + W_HL + 16384);
    TC_FENCE_BEFORE();
    FENCE_ASYNC();
    __syncthreads();
    if (wid == 0 && elect_one()) {
        issue_chunk(tb, uA0, uW, true);
        issue_chunk(tb, uA1, uW + 16384, false);
        TC_COMMIT(mb + 0);                                                // id8
    }
    wait_commit(mb, 8);
    TC_FENCE_AFTER();
    for (int ch = 0; ch < 4; ch++) {
        int c0 = 64 * half + 16 * ch;
        uint32_t r[16];
        LD16(r, tb + c0 + woff);
        TC_WAIT_LD();
#pragma unroll
        for (int j4 = 0; j4 < 4; j4++) {
            float4 v;
            v.x = __uint_as_float(r[4 * j4 + 0]) + b0o[c0 + 4 * j4 + 0];
            v.y = __uint_as_float(r[4 * j4 + 1]) + b0o[c0 + 4 * j4 + 1];
            v.z = __uint_as_float(r[4 * j4 + 2]) + b0o[c0 + 4 * j4 + 2];
            v.w = __uint_as_float(r[4 * j4 + 3]) + b0o[c0 + 4 * j4 + 3];
            *reinterpret_cast<float4*>(out0 + (size_t)(t0 + tok) * 128 + c0 + 4 * j4) = v;
        }
    }
    conv_block<128>(W1o,       192, sWh,             sWh + W_HL);
    conv_block<128>(W1o + 64,  192, sWh + 16384,     sWh + W_HL + 16384);
    conv_block<128>(W1o + 128, 192, sWh + 2 * 16384, sWh + W_HL + 2 * 16384);
    TC_FENCE_BEFORE();
    FENCE_ASYNC();
    __syncthreads();

    // ======== Phase 4: per component: Y1_i + GEMM4_i + out1_i ========
#pragma unroll 1
    for (int i = 0; i < 3; i++) {
        const int i1 = (i + 1 == 3) ? 0 : i + 1;
        const int i2 = (i + 2 >= 3) ? i - 1 : i + 2;
        const float* p0r = sP0 + tok * P0S;
#pragma unroll 1
        for (int c = 0; c < 3; c++) {
            int cc = 3 * i + c;
            char* ab = (cc & 1) ? sA1 : sA0;
            uint32_t ua = (cc & 1) ? uA1 : uA0;
            // compute Y values into registers BEFORE the buffer-reuse wait
            float y[2][16];
            for (int ch = 0; ch < 2; ch++) {
                int r0 = 32 * half + 16 * ch;
                if (c == 0) {                 // q011 = z0_l * z1_r[i]
                    uint32_t rv[16];
                    LD16(rv, tb + 128 + 128 * i + 64 + r0 + woff);
                    TC_WAIT_LD();
#pragma unroll
                    for (int j = 0; j < 16; j++)
                        y[ch][j] = p0r[r0 + j] * __uint_as_float(rv[j]);
                } else if (c == 1) {          // q101 = z1_l[i] * z0_r
                    uint32_t lv[16];
                    LD16(lv, tb + 128 + 128 * i + r0 + woff);
                    TC_WAIT_LD();
#pragma unroll
                    for (int j = 0; j < 16; j++)
                        y[ch][j] = __uint_as_float(lv[j]) * p0r[64 + r0 + j];
                } else {                      // q111 = l_i1*r_i2 - l_i2*r_i1
                    uint32_t va[16], vb[16], vc[16], vd[16];
                    LD16(va, tb + 128 + 128 * i1 + r0 + woff);
                    LD16(vb, tb + 128 + 128 * i2 + 64 + r0 + woff);
                    LD16(vc, tb + 128 + 128 * i2 + r0 + woff);
                    LD16(vd, tb + 128 + 128 * i1 + 64 + r0 + woff);
                    TC_WAIT_LD();
#pragma unroll
                    for (int j = 0; j < 16; j++)
                        y[ch][j] = __uint_as_float(va[j]) * __uint_as_float(vb[j])
                                 - __uint_as_float(vc[j]) * __uint_as_float(vd[j]);
                }
            }
            if (cc >= 2) wait_commit(mb, 9 + cc - 2);
#pragma unroll
            for (int ch = 0; ch < 2; ch++) {
                int r0 = 32 * half + 16 * ch;
#pragma unroll
                for (int j = 0; j < 16; j += 2)
                    cvt_store(y[ch][j], y[ch][j + 1], ab, ab + A_HL,
                              swz(tok * 128 + 2 * (r0 + j)));
            }
            FENCE_ASYNC();
            __syncthreads();
            if (wid == 0 && elect_one()) {
                issue_chunk(tb, ua, uW + 16384 * c, c == 0);
                TC_COMMIT(mb + 8 * ((9 + cc) & 3));                       // id 9+cc
            }
        }
        wait_commit(mb, 9 + 3 * i + 2);
        TC_FENCE_AFTER();
        for (int ch = 0; ch < 4; ch++) {
            int c0 = 64 * half + 16 * ch;
            uint32_t r[16];
            LD16(r, tb + c0 + woff);
            TC_WAIT_LD();
#pragma unroll
            for (int j4 = 0; j4 < 4; j4++) {
                float4 v;
                v.x = __uint_as_float(r[4 * j4 + 0]);
                v.y = __uint_as_float(r[4 * j4 + 1]);
                v.z = __uint_as_float(r[4 * j4 + 2]);
                v.w = __uint_as_float(r[4 * j4 + 3]);
                *reinterpret_cast<float4*>(out1 + (size_t)(t0 + tok) * 384 + i * 128 + c0 + 4 * j4) = v;
            }
        }
        TC_FENCE_BEFORE();
        __syncthreads();
    }

    __syncthreads();
    if (wid == 0) {
        TC_RELINQ();
        TC_DEALLOC(tb, 512);
    }
#endif  // ETP_TC_OK
}

// ============================== launcher ===================================
extern "C" void kernel_launch(void* const* d_in, const int* in_sizes, int n_in,
                              void* d_out, int out_size) {
    (void)in_sizes; (void)n_in; (void)out_size;
    cudaFuncSetAttribute(etp_tc, cudaFuncAttributeMaxDynamicSharedMemorySize,
                         tc::SMEM_BYTES);
    etp_tc<<<tc::NCTA, tc::NT, tc::SMEM_BYTES>>>(
        (const float*)d_in[0],  (const float*)d_in[1],
        (const float*)d_in[2],  (const float*)d_in[3],
        (const float*)d_in[4],  (const float*)d_in[5],
        (const float*)d_in[6],  (const float*)d_in[7],
        (const float*)d_in[8],  (const float*)d_in[9],
        (const float*)d_in[10], (float*)d_out);
}

// round 9
// speedup vs baseline: 3.5099x; 1.0789x over previous
#include <cuda_runtime.h>
#include <cuda_bf16.h>
#include <cstdint>

// ===========================================================================
// ElementwiseTensorProducts on tcgen05 (sm_103a), bf16 hi/lo split (3-pass).
// R5: weights pre-converted/pre-swizzled once by conv_w kernel into g_W;
//     main kernel stages weight chunks via cp.async scheduled early under
//     MMA/LDTM work. Activation converts unchanged (R4-proven).
// ===========================================================================

#if defined(__CUDA_ARCH_FEAT_SM103_ALL) || defined(__CUDA_ARCH_FEAT_SM100_ALL) || \
    defined(__CUDA_ARCH_FEAT_SM101_ALL) || defined(__CUDA_ARCH_SPECIFIC__) ||     \
    defined(__CUDA_ARCH_FAMILY_SPECIFIC__)
#define ETP_TC_OK 1
#endif

#define DI __device__ __forceinline__

namespace tc {
constexpr int BN  = 65536;
constexpr int TOK = 128;
constexpr int NT  = 256;
constexpr int NCTA = BN / TOK;          // 512

constexpr int OFF_MBAR = 64;            // 4 mbarriers
constexpr int OFF_W    = 1024;          // 3 slots x 16KB hi ; lo at +W_HL
constexpr int W_HL     = 49152;
constexpr int OFF_A    = OFF_W + 2 * W_HL;   // 99328
constexpr int A_HL     = 16384;
constexpr int A_BUF    = 32768;
constexpr int OFF_P0   = OFF_A + 2 * A_BUF;  // 164864
constexpr int P0S      = 129;
constexpr int SMEM_BYTES = OFF_P0 + TOK * P0S * 4;   // 230912

constexpr int CHUNK = 32768;            // bytes per converted weight chunk (hi+lo)

constexpr uint32_t IDESC =
    (1u << 4) | (1u << 7) | (1u << 10) | ((128u / 8) << 17) | ((128u / 16) << 24);

constexpr uint64_t DESC_BASE_SW128 =
    (uint64_t(2) << 61) | (uint64_t(1) << 46) | (uint64_t(64) << 32) | (uint64_t(1) << 16);
}

// Pre-converted weights: 9 chunks x (16KB hi | 16KB lo), SW128-swizzled.
// chunks 0,1: [W0l;W0r] K-halves; 2,3: [W1l;W1r]; 4,5: W0o; 6,7,8: W1o.
__device__ __align__(1024) unsigned char g_W[9 * tc::CHUNK];

DI int swz(int off) { return off ^ ((off >> 3) & 0x70); }

DI void cvt_pack(float x0, float x1, uint32_t& hp, uint32_t& lp) {
    __nv_bfloat16 h0 = __float2bfloat16(x0), h1 = __float2bfloat16(x1);
    float r0 = x0 - __bfloat162float(h0), r1 = x1 - __bfloat162float(h1);
    __nv_bfloat16 l0 = __float2bfloat16(r0), l1 = __float2bfloat16(r1);
    hp = (uint32_t)__bfloat16_as_ushort(h0) | ((uint32_t)__bfloat16_as_ushort(h1) << 16);
    lp = (uint32_t)__bfloat16_as_ushort(l0) | ((uint32_t)__bfloat16_as_ushort(l1) << 16);
}

// ---------------- weight pre-conversion kernel (tiny, runs once/call) ------
__global__ void conv_w(const float* __restrict__ W0l, const float* __restrict__ W0r,
                       const float* __restrict__ W1l, const float* __restrict__ W1r,
                       const float* __restrict__ W0o, const float* __restrict__ W1o) {
    int idx = blockIdx.x * blockDim.x + threadIdx.x;    // 9*4096
    if (idx >= 9 * 4096) return;
    int c  = idx >> 12;
    int r  = (idx >> 5) & 127;
    int kp = idx & 31;
    int k  = ((c >= 6) ? (c - 6) : (c & 1)) * 64 + kp * 2;
    const float* src;
    if (c < 2)      src = (r < 64) ? W0l + r * 128 : W0r + (r - 64) * 128;
    else if (c < 4) src = (r < 64) ? W1l + r * 128 : W1r + (r - 64) * 128;
    else if (c < 6) src = W0o + r * 128;
    else            src = W1o + r * 192;
    float2 v = *reinterpret_cast<const float2*>(src + k);
    uint32_t hp, lp;
    cvt_pack(v.x, v.y, hp, lp);
    int so = c * tc::CHUNK + swz(r * 128 + kp * 4);
    *(uint32_t*)(g_W + so)         = hp;
    *(uint32_t*)(g_W + so + 16384) = lp;
}

DI uint32_t smem_u32(const void* p) {
    uint32_t a;
    asm("{ .reg .u64 t; cvta.to.shared.u64 t, %1; cvt.u32.u64 %0, t; }" : "=r"(a) : "l"(p));
    return a;
}

#ifdef ETP_TC_OK
DI uint32_t elect_one() {
    uint32_t p;
    asm volatile("{ .reg .pred p; elect.sync _|p, 0xFFFFFFFF; selp.b32 %0,1,0,p; }" : "=r"(p));
    return p;
}
#define MBAR_INIT(a, n) \
    asm volatile("mbarrier.init.shared.b64 [%0], %1;" :: "r"(a), "r"(n) : "memory")
#define MBAR_WAIT(a, par) do {                                              \
    uint32_t _m = (a), _p = (par), _d;                                      \
    asm volatile("{ .reg .pred p; mbarrier.try_wait.parity.acquire.cta.shared::cta.b64 p, [%1], %2;" \
                 " selp.b32 %0,1,0,p; }" : "=r"(_d) : "r"(_m), "r"(_p) : "memory");          \
    if (!_d) asm volatile("{ .reg .pred P1; W%=:"                           \
        " mbarrier.try_wait.parity.acquire.cta.shared::cta.b64 P1, [%0], %1, 0x989680;" \
        " @P1 bra.uni D%=; bra.uni W%=; D%=: }" :: "r"(_m), "r"(_p) : "memory"); \
} while (0)
#define TC_ALLOC(sa, n)  asm volatile("tcgen05.alloc.cta_group::1.sync.aligned.shared::cta.b32 [%0], %1;" :: "r"(sa), "r"(n) : "memory")
#define TC_DEALLOC(t, n) asm volatile("tcgen05.dealloc.cta_group::1.sync.aligned.b32 %0, %1;" :: "r"(t), "r"(n))
#define TC_RELINQ()      asm volatile("tcgen05.relinquish_alloc_permit.cta_group::1.sync.aligned;")
#define TC_COMMIT(mb)    asm volatile("tcgen05.commit.cta_group::1.mbarrier::arrive::one.shared::cluster.b64 [%0];" :: "r"(mb) : "memory")
#define TC_WAIT_LD()     asm volatile("tcgen05.wait::ld.sync.aligned;" ::: "memory")
#define TC_FENCE_BEFORE() asm volatile("tcgen05.fence::before_thread_sync;" ::: "memory")
#define TC_FENCE_AFTER()  asm volatile("tcgen05.fence::after_thread_sync;" ::: "memory")
#define FENCE_ASYNC()     asm volatile("fence.proxy.async.shared::cta;" ::: "memory")
#define CP_COMMIT()       asm volatile("cp.async.commit_group;" ::: "memory")
#define CP_WAIT_ALL()     asm volatile("cp.async.wait_group 0;" ::: "memory")

#define LD16(r, a) \
    asm volatile("tcgen05.ld.sync.aligned.32x32b.x16.b32 " \
        "{%0,%1,%2,%3,%4,%5,%6,%7,%8,%9,%10,%11,%12,%13,%14,%15}, [%16];" \
        : "=r"((r)[0]), "=r"((r)[1]), "=r"((r)[2]), "=r"((r)[3]),   \
          "=r"((r)[4]), "=r"((r)[5]), "=r"((r)[6]), "=r"((r)[7]),   \
          "=r"((r)[8]), "=r"((r)[9]), "=r"((r)[10]), "=r"((r)[11]), \
          "=r"((r)[12]), "=r"((r)[13]), "=r"((r)[14]), "=r"((r)[15]) \
        : "r"(a))

DI uint64_t mkdesc(uint32_t sa) {
    return tc::DESC_BASE_SW128 | (uint64_t(sa >> 4) & 0x3FFF);
}
DI void mma_ss(uint32_t d, uint64_t ad, uint64_t bd, uint32_t en) {
    asm volatile("{ .reg .pred p; setp.ne.u32 p, %4, 0;"
                 " tcgen05.mma.cta_group::1.kind::f16 [%0], %1, %2, %3, {%5,%5,%5,%5}, p; }"
                 :: "r"(d), "l"(ad), "l"(bd), "r"(tc::IDESC), "r"(en), "r"(0u) : "memory");
}
DI void issue_chunk(uint32_t d, uint32_t a, uint32_t w, bool first) {
    uint64_t ah = mkdesc(a), al = mkdesc(a + tc::A_HL);
    uint64_t wh = mkdesc(w), wl = mkdesc(w + tc::W_HL);
#pragma unroll
    for (int s = 0; s < 4; s++) {
        mma_ss(d, ah + 2 * s, wh + 2 * s, (first && s == 0) ? 0u : 1u);
        mma_ss(d, ah + 2 * s, wl + 2 * s, 1u);
        mma_ss(d, al + 2 * s, wh + 2 * s, 1u);
    }
}
DI void wait_commit(uint32_t mb, int idx) {
    MBAR_WAIT(mb + (idx & 3) * 8, (idx >> 2) & 1);
}

DI void cvt_store(float x0, float x1, char* dh, char* dl, int so) {
    uint32_t hp, lp;
    cvt_pack(x0, x1, hp, lp);
    *(uint32_t*)(dh + so) = hp;
    *(uint32_t*)(dl + so) = lp;
}

// cp.async staging of one converted weight chunk (hi+lo) into W slot
DI void cpa16(uint32_t d, const void* s) {
    asm volatile("cp.async.cg.shared.global [%0], [%1], 16;" :: "r"(d), "l"(s) : "memory");
}
DI void copy_wchunk(uint32_t slot_addr, const unsigned char* g) {
#pragma unroll
    for (int it = 0; it < 4; it++) {
        int off = (threadIdx.x + it * tc::NT) * 16;
        cpa16(slot_addr + off, g + off);                              // hi
        cpa16(slot_addr + tc::W_HL + off, g + 16384 + off);           // lo
    }
}

// ---- fully unrolled activation load/convert (max MLP) ----
template <int ROWS>
DI void ld_regs(const float* __restrict__ g, int gs, float2 (&v)[ROWS * 32 / tc::NT]) {
    constexpr int IT = ROWS * 32 / tc::NT;
#pragma unroll
    for (int it = 0; it < IT; it++) {
        int idx = threadIdx.x + it * tc::NT;
        int row = idx >> 5, kp = idx & 31;
        v[it] = *reinterpret_cast<const float2*>(g + (long long)row * gs + kp * 2);
    }
}
template <int ROWS>
DI void st_regs(const float2 (&v)[ROWS * 32 / tc::NT], char* dh, char* dl) {
    constexpr int IT = ROWS * 32 / tc::NT;
#pragma unroll
    for (int it = 0; it < IT; it++) {
        int idx = threadIdx.x + it * tc::NT;
        int row = idx >> 5, kp = idx & 31;
        cvt_store(v[it].x, v[it].y, dh, dl, swz(row * 128 + kp * 4));
    }
}
#endif  // ETP_TC_OK

__global__ __launch_bounds__(tc::NT, 1) __cluster_dims__(1, 1, 1)
void etp_tc(const float* __restrict__ z0,  const float* __restrict__ z1,
            const float* __restrict__ b0l, const float* __restrict__ b0r,
            const float* __restrict__ b0o, float* __restrict__ out) {
#ifdef ETP_TC_OK
    using namespace tc;
    extern __shared__ char sm[];
    const uint32_t smb = smem_u32(sm);
    const int tid = threadIdx.x, wid = tid >> 5, lane = tid & 31;
    const int t0 = blockIdx.x * TOK;

    char* sA0 = sm + OFF_A;
    char* sA1 = sA0 + A_BUF;
    float* sP0 = reinterpret_cast<float*>(sm + OFF_P0);
    const uint32_t mb = smb + OFF_MBAR;
    const uint32_t uW = smb + OFF_W, uA0 = smb + OFF_A, uA1 = uA0 + A_BUF;
    float* out0 = out;
    float* out1 = out + (size_t)BN * 128;

    if (tid == 0)
        for (int s = 0; s < 4; s++) MBAR_INIT(mb + 8 * s, 1);
    if (wid == 0) TC_ALLOC(smb, 512);

    // ---- stage GEMM1 weights (slots 0,1) while z0 loads are in flight ----
    copy_wchunk(uW,          g_W + 0 * CHUNK);
    copy_wchunk(uW + 16384,  g_W + 1 * CHUNK);
    CP_COMMIT();

    __syncthreads();
    uint32_t tb;
    asm volatile("ld.shared.b32 %0, [%1];" : "=r"(tb) : "r"(smb));

    const uint32_t woff = (uint32_t)(wid & 3) << 21;
    const int half = wid >> 2;
    const int tok = 32 * (wid & 3) + lane;

    // ======== Phase 1: GEMM1 (P0 -> cols 0-127) ========
    {
        float2 v0[16], v1[16];
        ld_regs<128>(z0 + (size_t)t0 * 128,      128, v0);
        ld_regs<128>(z0 + (size_t)t0 * 128 + 64, 128, v1);
        st_regs<128>(v0, sA0, sA0 + A_HL);
        CP_WAIT_ALL();
        FENCE_ASYNC();
        __syncthreads();
        if (wid == 0 && elect_one()) { issue_chunk(tb, uA0, uW, true);  TC_COMMIT(mb + 0); }  // id0
        st_regs<128>(v1, sA1, sA1 + A_HL);
        FENCE_ASYNC();
        __syncthreads();
        if (wid == 0 && elect_one()) { issue_chunk(tb, uA1, uW + 16384, false); TC_COMMIT(mb + 8); } // id1
    }

    // stage g2 -> slot2 (free) while GEMM1 runs
    copy_wchunk(uW + 2 * 16384, g_W + 2 * CHUNK);
    CP_COMMIT();

    // ---- P0 drain (+bias); stage g3 -> slot0, g4 -> slot1 ----
    wait_commit(mb, 1);
    TC_FENCE_AFTER();
    copy_wchunk(uW,         g_W + 3 * CHUNK);   // slot0 free (commit1 waited)
    copy_wchunk(uW + 16384, g_W + 4 * CHUNK);   // slot1 free
    CP_COMMIT();
    for (int ch = 0; ch < 4; ch++) {
        int c0 = 64 * half + 16 * ch;
        uint32_t r[16];
        LD16(r, tb + c0 + woff);
        TC_WAIT_LD();
#pragma unroll
        for (int j = 0; j < 16; j++) {
            int n = c0 + j;
            float b = (n < 64) ? b0l[n] : b0r[n - 64];
            sP0[tok * P0S + n] = __uint_as_float(r[j]) + b;
        }
    }

    // ======== Phase 2: GEMM2 (P1_i -> cols 128+128i); W: c0->slot2, c1->slot0
    for (int i = 0; i < 3; i++)
#pragma unroll 1
        for (int c = 0; c < 2; c++) {
            int cc = 2 * i + c;
            char* ab = (cc & 1) ? sA1 : sA0;
            uint32_t ua = (cc & 1) ? uA1 : uA0;
            float2 v[16];
            ld_regs<128>(z1 + (size_t)t0 * 384 + i * 128 + 64 * c, 384, v);
            if (cc >= 2) wait_commit(mb, cc);       // A-buffer guard
            st_regs<128>(v, ab, ab + A_HL);
            if (cc == 0) CP_WAIT_ALL();             // g2,g3 staged before first use
            FENCE_ASYNC();
            __syncthreads();
            if (wid == 0 && elect_one()) {
                issue_chunk(tb + 128 + 128 * i, ua, uW + 16384 * (c == 0 ? 2 : 0), c == 0);
                TC_COMMIT(mb + 8 * ((2 + cc) & 3)); // id 2+cc
            }
        }

    // slot2's last MMA use is id6 -> stage g5 -> slot2
    wait_commit(mb, 6);
    copy_wchunk(uW + 2 * 16384, g_W + 5 * CHUNK);
    CP_COMMIT();

    // ======== Phase 3: Y0 + GEMM3 + out0 ========
    wait_commit(mb, 7);
    TC_FENCE_AFTER();
    {
        const float* p0r = sP0 + tok * P0S;
        for (int ch = 0; ch < 2; ch++) {
            int r0 = 32 * half + 16 * ch;
            float s[16];
#pragma unroll
            for (int j = 0; j < 16; j++) s[j] = 0.f;
#pragma unroll
            for (int i = 0; i < 3; i++) {
                uint32_t lv[16], rv[16];
                LD16(lv, tb + 128 + 128 * i + r0 + woff);
                LD16(rv, tb + 128 + 128 * i + 64 + r0 + woff);
                TC_WAIT_LD();
#pragma unroll
                for (int j = 0; j < 16; j++)
                    s[j] += __uint_as_float(lv[j]) * __uint_as_float(rv[j]);
            }
#pragma unroll
            for (int j = 0; j < 16; j += 2) {
                int k = r0 + j;
                float a0 = p0r[k] * p0r[64 + k];
                float a1 = p0r[k + 1] * p0r[64 + k + 1];
                cvt_store(a0, a1, sA0, sA0 + A_HL, swz(tok * 128 + 2 * k));
                cvt_store(s[j], s[j + 1], sA1, sA1 + A_HL, swz(tok * 128 + 2 * k));
            }
        }
    }
    CP_WAIT_ALL();
    FENCE_ASYNC();
    __syncthreads();
    if (wid == 0 && elect_one()) {
        issue_chunk(tb, uA0, uW + 16384,     true);   // g4 = W0o chunk0 (slot1)
        issue_chunk(tb, uA1, uW + 2 * 16384, false);  // g5 = W0o chunk1 (slot2)
        TC_COMMIT(mb + 0);                            // id8
    }
    copy_wchunk(uW, g_W + 6 * CHUNK);                 // g6 -> slot0 (free after id7)
    CP_COMMIT();

    wait_commit(mb, 8);
    TC_FENCE_AFTER();
    for (int ch = 0; ch < 4; ch++) {
        int c0 = 64 * half + 16 * ch;
        uint32_t r[16];
        LD16(r, tb + c0 + woff);
        TC_WAIT_LD();
#pragma unroll
        for (int j4 = 0; j4 < 4; j4++) {
            float4 v;
            v.x = __uint_as_float(r[4 * j4 + 0]) + b0o[c0 + 4 * j4 + 0];
            v.y = __uint_as_float(r[4 * j4 + 1]) + b0o[c0 + 4 * j4 + 1];
            v.z = __uint_as_float(r[4 * j4 + 2]) + b0o[c0 + 4 * j4 + 2];
            v.w = __uint_as_float(r[4 * j4 + 3]) + b0o[c0 + 4 * j4 + 3];
            *reinterpret_cast<float4*>(out0 + (size_t)(t0 + tok) * 128 + c0 + 4 * j4) = v;
        }
    }
    copy_wchunk(uW + 16384,     g_W + 7 * CHUNK);     // g7 -> slot1 (free after id8)
    copy_wchunk(uW + 2 * 16384, g_W + 8 * CHUNK);     // g8 -> slot2
    CP_COMMIT();

    // ======== Phase 4: per component: Y1_i + GEMM4_i + out1_i ========
#pragma unroll 1
    for (int i = 0; i < 3; i++) {
        const int i1 = (i + 1 == 3) ? 0 : i + 1;
        const int i2 = (i + 2 >= 3) ? i - 1 : i + 2;
        const float* p0r = sP0 + tok * P0S;
#pragma unroll 1
        for (int c = 0; c < 3; c++) {
            int cc = 3 * i + c;
            char* ab = (cc & 1) ? sA1 : sA0;
            uint32_t ua = (cc & 1) ? uA1 : uA0;
            float y[2][16];
            for (int ch = 0; ch < 2; ch++) {
                int r0 = 32 * half + 16 * ch;
                if (c == 0) {                 // q011 = z0_l * z1_r[i]
                    uint32_t rv[16];
                    LD16(rv, tb + 128 + 128 * i + 64 + r0 + woff);
                    TC_WAIT_LD();
#pragma unroll
                    for (int j = 0; j < 16; j++)
                        y[ch][j] = p0r[r0 + j] * __uint_as_float(rv[j]);
                } else if (c == 1) {          // q101 = z1_l[i] * z0_r
                    uint32_t lv[16];
                    LD16(lv, tb + 128 + 128 * i + r0 + woff);
                    TC_WAIT_LD();
#pragma unroll
                    for (int j = 0; j < 16; j++)
                        y[ch][j] = __uint_as_float(lv[j]) * p0r[64 + r0 + j];
                } else {                      // q111 = l_i1*r_i2 - l_i2*r_i1
                    uint32_t va[16], vb[16], vc[16], vd[16];
                    LD16(va, tb + 128 + 128 * i1 + r0 + woff);
                    LD16(vb, tb + 128 + 128 * i2 + 64 + r0 + woff);
                    LD16(vc, tb + 128 + 128 * i2 + r0 + woff);
                    LD16(vd, tb + 128 + 128 * i1 + 64 + r0 + woff);
                    TC_WAIT_LD();
#pragma unroll
                    for (int j = 0; j < 16; j++)
                        y[ch][j] = __uint_as_float(va[j]) * __uint_as_float(vb[j])
                                 - __uint_as_float(vc[j]) * __uint_as_float(vd[j]);
                }
            }
            if (cc >= 2) wait_commit(mb, 9 + cc - 2);   // A-buffer guard
#pragma unroll
            for (int ch = 0; ch < 2; ch++) {
                int r0 = 32 * half + 16 * ch;
#pragma unroll
                for (int j = 0; j < 16; j += 2)
                    cvt_store(y[ch][j], y[ch][j + 1], ab, ab + A_HL,
                              swz(tok * 128 + 2 * (r0 + j)));
            }
            if (cc == 0) CP_WAIT_ALL();                 // g6..g8 staged
            FENCE_ASYNC();
            __syncthreads();
            if (wid == 0 && elect_one()) {
                issue_chunk(tb, ua, uW + 16384 * c, c == 0);
                TC_COMMIT(mb + 8 * ((9 + cc) & 3));     // id 9+cc
            }
        }
        wait_commit(mb, 9 + 3 * i + 2);
        TC_FENCE_AFTER();
        for (int ch = 0; ch < 4; ch++) {
            int c0 = 64 * half + 16 * ch;
            uint32_t r[16];
            LD16(r, tb + c0 + woff);
            TC_WAIT_LD();
#pragma unroll
            for (int j4 = 0; j4 < 4; j4++) {
                float4 v;
                v.x = __uint_as_float(r[4 * j4 + 0]);
                v.y = __uint_as_float(r[4 * j4 + 1]);
                v.z = __uint_as_float(r[4 * j4 + 2]);
                v.w = __uint_as_float(r[4 * j4 + 3]);
                *reinterpret_cast<float4*>(out1 + (size_t)(t0 + tok) * 384 + i * 128 + c0 + 4 * j4) = v;
            }
        }
        TC_FENCE_BEFORE();
        __syncthreads();
    }

    __syncthreads();
    if (wid == 0) {
        TC_RELINQ();
        TC_DEALLOC(tb, 512);
    }
#endif  // ETP_TC_OK
}

// ============================== launcher ===================================
extern "C" void kernel_launch(void* const* d_in, const int* in_sizes, int n_in,
                              void* d_out, int out_size) {
    (void)in_sizes; (void)n_in; (void)out_size;
    cudaFuncSetAttribute(etp_tc, cudaFuncAttributeMaxDynamicSharedMemorySize,
                         tc::SMEM_BYTES);

    const float* z0  = (const float*)d_in[0];
    const float* z1  = (const float*)d_in[1];
    const float* W0l = (const float*)d_in[2];
    const float* b0l = (const float*)d_in[3];
    const float* W0r = (const float*)d_in[4];
    const float* b0r = (const float*)d_in[5];
    const float* W1l = (const float*)d_in[6];
    const float* W1r = (const float*)d_in[7];
    const float* W0o = (const float*)d_in[8];
    const float* b0o = (const float*)d_in[9];
    const float* W1o = (const float*)d_in[10];

    conv_w<<<144, 256>>>(W0l, W0r, W1l, W1r, W0o, W1o);
    etp_tc<<<tc::NCTA, tc::NT, tc::SMEM_BYTES>>>(z0, z1, b0l, b0r, b0o,
                                                 (float*)d_out);
}

// round 10
// speedup vs baseline: 3.9839x; 1.1351x over previous
#include <cuda_runtime.h>
#include <cuda_bf16.h>
#include <cstdint>

// ===========================================================================
// ElementwiseTensorProducts on tcgen05 (sm_103a), bf16 hi/lo split (3-pass).
// R10: NT=512 (16 warps, 4/SMSP) halves per-warp work & doubles latency
//      hiding; fast truncation-based hi/lo split (PRMT + cvt.rn.bf16x2).
//      Phase/commit schedule identical to R5 (proven).
// ===========================================================================

#if defined(__CUDA_ARCH_FEAT_SM103_ALL) || defined(__CUDA_ARCH_FEAT_SM100_ALL) || \
    defined(__CUDA_ARCH_FEAT_SM101_ALL) || defined(__CUDA_ARCH_SPECIFIC__) ||     \
    defined(__CUDA_ARCH_FAMILY_SPECIFIC__)
#define ETP_TC_OK 1
#endif

#define DI __device__ __forceinline__

namespace tc {
constexpr int BN  = 65536;
constexpr int TOK = 128;
constexpr int NT  = 512;                // 16 warps
constexpr int NCTA = BN / TOK;          // 512

constexpr int OFF_MBAR = 64;            // 4 mbarriers
constexpr int OFF_W    = 1024;          // 3 slots x 16KB hi ; lo at +W_HL
constexpr int W_HL     = 49152;
constexpr int OFF_A    = OFF_W + 2 * W_HL;   // 99328
constexpr int A_HL     = 16384;
constexpr int A_BUF    = 32768;
constexpr int OFF_P0   = OFF_A + 2 * A_BUF;  // 164864
constexpr int P0S      = 129;
constexpr int SMEM_BYTES = OFF_P0 + TOK * P0S * 4;   // 230912

constexpr int CHUNK = 32768;            // bytes per converted weight chunk (hi+lo)

constexpr uint32_t IDESC =
    (1u << 4) | (1u << 7) | (1u << 10) | ((128u / 8) << 17) | ((128u / 16) << 24);

constexpr uint64_t DESC_BASE_SW128 =
    (uint64_t(2) << 61) | (uint64_t(1) << 46) | (uint64_t(64) << 32) | (uint64_t(1) << 16);
}

// Pre-converted weights: 9 chunks x (16KB hi | 16KB lo), SW128-swizzled.
// chunks 0,1: [W0l;W0r] K-halves; 2,3: [W1l;W1r]; 4,5: W0o; 6,7,8: W1o.
__device__ __align__(1024) unsigned char g_W[9 * tc::CHUNK];

DI int swz(int off) { return off ^ ((off >> 3) & 0x70); }

DI void cvt_pack_rn(float x0, float x1, uint32_t& hp, uint32_t& lp) {
    __nv_bfloat16 h0 = __float2bfloat16(x0), h1 = __float2bfloat16(x1);
    float r0 = x0 - __bfloat162float(h0), r1 = x1 - __bfloat162float(h1);
    __nv_bfloat16 l0 = __float2bfloat16(r0), l1 = __float2bfloat16(r1);
    hp = (uint32_t)__bfloat16_as_ushort(h0) | ((uint32_t)__bfloat16_as_ushort(h1) << 16);
    lp = (uint32_t)__bfloat16_as_ushort(l0) | ((uint32_t)__bfloat16_as_ushort(l1) << 16);
}

// ---------------- weight pre-conversion kernel (tiny, runs once/call) ------
__global__ void conv_w(const float* __restrict__ W0l, const float* __restrict__ W0r,
                       const float* __restrict__ W1l, const float* __restrict__ W1r,
                       const float* __restrict__ W0o, const float* __restrict__ W1o) {
    int idx = blockIdx.x * blockDim.x + threadIdx.x;    // 9*4096
    if (idx >= 9 * 4096) return;
    int c  = idx >> 12;
    int r  = (idx >> 5) & 127;
    int kp = idx & 31;
    int k  = ((c >= 6) ? (c - 6) : (c & 1)) * 64 + kp * 2;
    const float* src;
    if (c < 2)      src = (r < 64) ? W0l + r * 128 : W0r + (r - 64) * 128;
    else if (c < 4) src = (r < 64) ? W1l + r * 128 : W1r + (r - 64) * 128;
    else if (c < 6) src = W0o + r * 128;
    else            src = W1o + r * 192;
    float2 v = *reinterpret_cast<const float2*>(src + k);
    uint32_t hp, lp;
    cvt_pack_rn(v.x, v.y, hp, lp);
    int so = c * tc::CHUNK + swz(r * 128 + kp * 4);
    *(uint32_t*)(g_W + so)         = hp;
    *(uint32_t*)(g_W + so + 16384) = lp;
}

DI uint32_t smem_u32(const void* p) {
    uint32_t a;
    asm("{ .reg .u64 t; cvta.to.shared.u64 t, %1; cvt.u32.u64 %0, t; }" : "=r"(a) : "l"(p));
    return a;
}

#ifdef ETP_TC_OK
DI uint32_t elect_one() {
    uint32_t p;
    asm volatile("{ .reg .pred p; elect.sync _|p, 0xFFFFFFFF; selp.b32 %0,1,0,p; }" : "=r"(p));
    return p;
}
#define MBAR_INIT(a, n) \
    asm volatile("mbarrier.init.shared.b64 [%0], %1;" :: "r"(a), "r"(n) : "memory")
#define MBAR_WAIT(a, par) do {                                              \
    uint32_t _m = (a), _p = (par), _d;                                      \
    asm volatile("{ .reg .pred p; mbarrier.try_wait.parity.acquire.cta.shared::cta.b64 p, [%1], %2;" \
                 " selp.b32 %0,1,0,p; }" : "=r"(_d) : "r"(_m), "r"(_p) : "memory");          \
    if (!_d) asm volatile("{ .reg .pred P1; W%=:"                           \
        " mbarrier.try_wait.parity.acquire.cta.shared::cta.b64 P1, [%0], %1, 0x989680;" \
        " @P1 bra.uni D%=; bra.uni W%=; D%=: }" :: "r"(_m), "r"(_p) : "memory"); \
} while (0)
#define TC_ALLOC(sa, n)  asm volatile("tcgen05.alloc.cta_group::1.sync.aligned.shared::cta.b32 [%0], %1;" :: "r"(sa), "r"(n) : "memory")
#define TC_DEALLOC(t, n) asm volatile("tcgen05.dealloc.cta_group::1.sync.aligned.b32 %0, %1;" :: "r"(t), "r"(n))
#define TC_RELINQ()      asm volatile("tcgen05.relinquish_alloc_permit.cta_group::1.sync.aligned;")
#define TC_COMMIT(mb)    asm volatile("tcgen05.commit.cta_group::1.mbarrier::arrive::one.shared::cluster.b64 [%0];" :: "r"(mb) : "memory")
#define TC_WAIT_LD()     asm volatile("tcgen05.wait::ld.sync.aligned;" ::: "memory")
#define TC_FENCE_BEFORE() asm volatile("tcgen05.fence::before_thread_sync;" ::: "memory")
#define TC_FENCE_AFTER()  asm volatile("tcgen05.fence::after_thread_sync;" ::: "memory")
#define FENCE_ASYNC()     asm volatile("fence.proxy.async.shared::cta;" ::: "memory")
#define CP_COMMIT()       asm volatile("cp.async.commit_group;" ::: "memory")
#define CP_WAIT_ALL()     asm volatile("cp.async.wait_group 0;" ::: "memory")

#define LD16(r, a) \
    asm volatile("tcgen05.ld.sync.aligned.32x32b.x16.b32 " \
        "{%0,%1,%2,%3,%4,%5,%6,%7,%8,%9,%10,%11,%12,%13,%14,%15}, [%16];" \
        : "=r"((r)[0]), "=r"((r)[1]), "=r"((r)[2]), "=r"((r)[3]),   \
          "=r"((r)[4]), "=r"((r)[5]), "=r"((r)[6]), "=r"((r)[7]),   \
          "=r"((r)[8]), "=r"((r)[9]), "=r"((r)[10]), "=r"((r)[11]), \
          "=r"((r)[12]), "=r"((r)[13]), "=r"((r)[14]), "=r"((r)[15]) \
        : "r"(a))

DI uint64_t mkdesc(uint32_t sa) {
    return tc::DESC_BASE_SW128 | (uint64_t(sa >> 4) & 0x3FFF);
}
DI void mma_ss(uint32_t d, uint64_t ad, uint64_t bd, uint32_t en) {
    asm volatile("{ .reg .pred p; setp.ne.u32 p, %4, 0;"
                 " tcgen05.mma.cta_group::1.kind::f16 [%0], %1, %2, %3, {%5,%5,%5,%5}, p; }"
                 :: "r"(d), "l"(ad), "l"(bd), "r"(tc::IDESC), "r"(en), "r"(0u) : "memory");
}
DI void issue_chunk(uint32_t d, uint32_t a, uint32_t w, bool first) {
    uint64_t ah = mkdesc(a), al = mkdesc(a + tc::A_HL);
    uint64_t wh = mkdesc(w), wl = mkdesc(w + tc::W_HL);
#pragma unroll
    for (int s = 0; s < 4; s++) {
        mma_ss(d, ah + 2 * s, wh + 2 * s, (first && s == 0) ? 0u : 1u);
        mma_ss(d, ah + 2 * s, wl + 2 * s, 1u);
        mma_ss(d, al + 2 * s, wh + 2 * s, 1u);
    }
}
DI void wait_commit(uint32_t mb, int idx) {
    MBAR_WAIT(mb + (idx & 3) * 8, (idx >> 2) & 1);
}

// Fast hi/lo split: hi = top 16 bits (truncation), packed via one PRMT;
// lo = exact residual, packed via one cvt.rn.bf16x2.f32.
DI void cvt_store(float x0, float x1, char* dh, char* dl, int so) {
    uint32_t b0 = __float_as_uint(x0), b1 = __float_as_uint(x1);
    uint32_t hp;
    asm("prmt.b32 %0, %1, %2, 0x7632;" : "=r"(hp) : "r"(b0), "r"(b1));
    float h0 = __uint_as_float(b0 & 0xFFFF0000u);
    float h1 = __uint_as_float(b1 & 0xFFFF0000u);
    float l0 = x0 - h0, l1 = x1 - h1;
    uint32_t lp;
    asm("cvt.rn.bf16x2.f32 %0, %1, %2;" : "=r"(lp) : "f"(l1), "f"(l0));
    *(uint32_t*)(dh + so) = hp;
    *(uint32_t*)(dl + so) = lp;
}

// cp.async staging of one converted weight chunk (hi+lo) into W slot
DI void cpa16(uint32_t d, const void* s) {
    asm volatile("cp.async.cg.shared.global [%0], [%1], 16;" :: "r"(d), "l"(s) : "memory");
}
DI void copy_wchunk(uint32_t slot_addr, const unsigned char* g) {
#pragma unroll
    for (int it = 0; it < 16384 / 16 / tc::NT; it++) {
        int off = (threadIdx.x + it * tc::NT) * 16;
        cpa16(slot_addr + off, g + off);                              // hi
        cpa16(slot_addr + tc::W_HL + off, g + 16384 + off);           // lo
    }
}

// ---- fully unrolled activation load/convert (max MLP) ----
template <int ROWS>
DI void ld_regs(const float* __restrict__ g, int gs, float2 (&v)[ROWS * 32 / tc::NT]) {
    constexpr int IT = ROWS * 32 / tc::NT;
#pragma unroll
    for (int it = 0; it < IT; it++) {
        int idx = threadIdx.x + it * tc::NT;
        int row = idx >> 5, kp = idx & 31;
        v[it] = *reinterpret_cast<const float2*>(g + (long long)row * gs + kp * 2);
    }
}
template <int ROWS>
DI void st_regs(const float2 (&v)[ROWS * 32 / tc::NT], char* dh, char* dl) {
    constexpr int IT = ROWS * 32 / tc::NT;
#pragma unroll
    for (int it = 0; it < IT; it++) {
        int idx = threadIdx.x + it * tc::NT;
        int row = idx >> 5, kp = idx & 31;
        cvt_store(v[it].x, v[it].y, dh, dl, swz(row * 128 + kp * 4));
    }
}
#endif  // ETP_TC_OK

__global__ __launch_bounds__(tc::NT, 1) __cluster_dims__(1, 1, 1)
void etp_tc(const float* __restrict__ z0,  const float* __restrict__ z1,
            const float* __restrict__ b0l, const float* __restrict__ b0r,
            const float* __restrict__ b0o, float* __restrict__ out) {
#ifdef ETP_TC_OK
    using namespace tc;
    extern __shared__ char sm[];
    const uint32_t smb = smem_u32(sm);
    const int tid = threadIdx.x, wid = tid >> 5, lane = tid & 31;
    const int t0 = blockIdx.x * TOK;

    char* sA0 = sm + OFF_A;
    char* sA1 = sA0 + A_BUF;
    float* sP0 = reinterpret_cast<float*>(sm + OFF_P0);
    const uint32_t mb = smb + OFF_MBAR;
    const uint32_t uW = smb + OFF_W, uA0 = smb + OFF_A, uA1 = uA0 + A_BUF;
    float* out0 = out;
    float* out1 = out + (size_t)BN * 128;

    if (tid == 0)
        for (int s = 0; s < 4; s++) MBAR_INIT(mb + 8 * s, 1);
    if (wid == 0) TC_ALLOC(smb, 512);

    // ---- stage GEMM1 weights (slots 0,1) ----
    copy_wchunk(uW,          g_W + 0 * CHUNK);
    copy_wchunk(uW + 16384,  g_W + 1 * CHUNK);
    CP_COMMIT();

    __syncthreads();
    uint32_t tb;
    asm volatile("ld.shared.b32 %0, [%1];" : "=r"(tb) : "r"(smb));

    const int subp = wid & 3;                 // TMEM subpartition / token group
    const int half = wid >> 2;                // column quarter 0..3
    const uint32_t woff = (uint32_t)subp << 21;
    const int tok = 32 * subp + lane;

    // ======== Phase 1: GEMM1 (P0 -> cols 0-127) ========
    {
        float2 v0[8], v1[8];
        ld_regs<128>(z0 + (size_t)t0 * 128,      128, v0);
        ld_regs<128>(z0 + (size_t)t0 * 128 + 64, 128, v1);
        st_regs<128>(v0, sA0, sA0 + A_HL);
        CP_WAIT_ALL();
        FENCE_ASYNC();
        __syncthreads();
        if (wid == 0 && elect_one()) { issue_chunk(tb, uA0, uW, true);  TC_COMMIT(mb + 0); }  // id0
        st_regs<128>(v1, sA1, sA1 + A_HL);
        FENCE_ASYNC();
        __syncthreads();
        if (wid == 0 && elect_one()) { issue_chunk(tb, uA1, uW + 16384, false); TC_COMMIT(mb + 8); } // id1
    }

    // stage g2 -> slot2 (free) while GEMM1 runs
    copy_wchunk(uW + 2 * 16384, g_W + 2 * CHUNK);
    CP_COMMIT();

    // ---- P0 drain (+bias); stage g3 -> slot0, g4 -> slot1 ----
    wait_commit(mb, 1);
    TC_FENCE_AFTER();
    copy_wchunk(uW,         g_W + 3 * CHUNK);   // slot0 free (commit1 waited)
    copy_wchunk(uW + 16384, g_W + 4 * CHUNK);   // slot1 free
    CP_COMMIT();
#pragma unroll
    for (int ch = 0; ch < 2; ch++) {
        int c0 = 32 * half + 16 * ch;
        uint32_t r[16];
        LD16(r, tb + c0 + woff);
        TC_WAIT_LD();
#pragma unroll
        for (int j = 0; j < 16; j++) {
            int n = c0 + j;
            float b = (n < 64) ? b0l[n] : b0r[n - 64];
            sP0[tok * P0S + n] = __uint_as_float(r[j]) + b;
        }
    }

    // ======== Phase 2: GEMM2 (P1_i -> cols 128+128i); W: c0->slot2, c1->slot0
    for (int i = 0; i < 3; i++)
#pragma unroll 1
        for (int c = 0; c < 2; c++) {
            int cc = 2 * i + c;
            char* ab = (cc & 1) ? sA1 : sA0;
            uint32_t ua = (cc & 1) ? uA1 : uA0;
            float2 v[8];
            ld_regs<128>(z1 + (size_t)t0 * 384 + i * 128 + 64 * c, 384, v);
            if (cc >= 2) wait_commit(mb, cc);       // A-buffer guard
            st_regs<128>(v, ab, ab + A_HL);
            if (cc == 0) CP_WAIT_ALL();             // g2,g3 staged before first use
            FENCE_ASYNC();
            __syncthreads();
            if (wid == 0 && elect_one()) {
                issue_chunk(tb + 128 + 128 * i, ua, uW + 16384 * (c == 0 ? 2 : 0), c == 0);
                TC_COMMIT(mb + 8 * ((2 + cc) & 3)); // id 2+cc
            }
        }

    // slot2's last MMA use is id6 -> stage g5 -> slot2
    wait_commit(mb, 6);
    copy_wchunk(uW + 2 * 16384, g_W + 5 * CHUNK);
    CP_COMMIT();

    // ======== Phase 3: Y0 + GEMM3 + out0 ========
    wait_commit(mb, 7);
    TC_FENCE_AFTER();
    {
        const float* p0r = sP0 + tok * P0S;
        const int r0 = 16 * half;
        float s[16];
#pragma unroll
        for (int j = 0; j < 16; j++) s[j] = 0.f;
#pragma unroll
        for (int i = 0; i < 3; i++) {
            uint32_t lv[16], rv[16];
            LD16(lv, tb + 128 + 128 * i + r0 + woff);
            LD16(rv, tb + 128 + 128 * i + 64 + r0 + woff);
            TC_WAIT_LD();
#pragma unroll
            for (int j = 0; j < 16; j++)
                s[j] += __uint_as_float(lv[j]) * __uint_as_float(rv[j]);
        }
#pragma unroll
        for (int j = 0; j < 16; j += 2) {
            int k = r0 + j;
            float a0 = p0r[k] * p0r[64 + k];
            float a1 = p0r[k + 1] * p0r[64 + k + 1];
            cvt_store(a0, a1, sA0, sA0 + A_HL, swz(tok * 128 + 2 * k));
            cvt_store(s[j], s[j + 1], sA1, sA1 + A_HL, swz(tok * 128 + 2 * k));
        }
    }
    CP_WAIT_ALL();
    FENCE_ASYNC();
    __syncthreads();
    if (wid == 0 && elect_one()) {
        issue_chunk(tb, uA0, uW + 16384,     true);   // g4 = W0o chunk0 (slot1)
        issue_chunk(tb, uA1, uW + 2 * 16384, false);  // g5 = W0o chunk1 (slot2)
        TC_COMMIT(mb + 0);                            // id8
    }
    copy_wchunk(uW, g_W + 6 * CHUNK);                 // g6 -> slot0 (free after id7)
    CP_COMMIT();

    wait_commit(mb, 8);
    TC_FENCE_AFTER();
#pragma unroll
    for (int ch = 0; ch < 2; ch++) {
        int c0 = 32 * half + 16 * ch;
        uint32_t r[16];
        LD16(r, tb + c0 + woff);
        TC_WAIT_LD();
#pragma unroll
        for (int j4 = 0; j4 < 4; j4++) {
            float4 v;
            v.x = __uint_as_float(r[4 * j4 + 0]) + b0o[c0 + 4 * j4 + 0];
            v.y = __uint_as_float(r[4 * j4 + 1]) + b0o[c0 + 4 * j4 + 1];
            v.z = __uint_as_float(r[4 * j4 + 2]) + b0o[c0 + 4 * j4 + 2];
            v.w = __uint_as_float(r[4 * j4 + 3]) + b0o[c0 + 4 * j4 + 3];
            *reinterpret_cast<float4*>(out0 + (size_t)(t0 + tok) * 128 + c0 + 4 * j4) = v;
        }
    }
    copy_wchunk(uW + 16384,     g_W + 7 * CHUNK);     // g7 -> slot1 (free after id8)
    copy_wchunk(uW + 2 * 16384, g_W + 8 * CHUNK);     // g8 -> slot2
    CP_COMMIT();

    // ======== Phase 4: per component: Y1_i + GEMM4_i + out1_i ========
#pragma unroll 1
    for (int i = 0; i < 3; i++) {
        const int i1 = (i + 1 == 3) ? 0 : i + 1;
        const int i2 = (i + 2 >= 3) ? i - 1 : i + 2;
        const float* p0r = sP0 + tok * P0S;
        const int r0 = 16 * half;
#pragma unroll 1
        for (int c = 0; c < 3; c++) {
            int cc = 3 * i + c;
            char* ab = (cc & 1) ? sA1 : sA0;
            uint32_t ua = (cc & 1) ? uA1 : uA0;
            float y[16];
            if (c == 0) {                 // q011 = z0_l * z1_r[i]
                uint32_t rv[16];
                LD16(rv, tb + 128 + 128 * i + 64 + r0 + woff);
                TC_WAIT_LD();
#pragma unroll
                for (int j = 0; j < 16; j++)
                    y[j] = p0r[r0 + j] * __uint_as_float(rv[j]);
            } else if (c == 1) {          // q101 = z1_l[i] * z0_r
                uint32_t lv[16];
                LD16(lv, tb + 128 + 128 * i + r0 + woff);
                TC_WAIT_LD();
#pragma unroll
                for (int j = 0; j < 16; j++)
                    y[j] = __uint_as_float(lv[j]) * p0r[64 + r0 + j];
            } else {                      // q111 = l_i1*r_i2 - l_i2*r_i1
                uint32_t va[16], vb[16];
                LD16(va, tb + 128 + 128 * i1 + r0 + woff);
                LD16(vb, tb + 128 + 128 * i2 + 64 + r0 + woff);
                TC_WAIT_LD();
#pragma unroll
                for (int j = 0; j < 16; j++)
                    y[j] = __uint_as_float(va[j]) * __uint_as_float(vb[j]);
                LD16(va, tb + 128 + 128 * i2 + r0 + woff);
                LD16(vb, tb + 128 + 128 * i1 + 64 + r0 + woff);
                TC_WAIT_LD();
#pragma unroll
                for (int j = 0; j < 16; j++)
                    y[j] -= __uint_as_float(va[j]) * __uint_as_float(vb[j]);
            }
            if (cc >= 2) wait_commit(mb, 9 + cc - 2);   // A-buffer guard
#pragma unroll
            for (int j = 0; j < 16; j += 2)
                cvt_store(y[j], y[j + 1], ab, ab + A_HL,
                          swz(tok * 128 + 2 * (r0 + j)));
            if (cc == 0) CP_WAIT_ALL();                 // g6..g8 staged
            FENCE_ASYNC();
            __syncthreads();
            if (wid == 0 && elect_one()) {
                issue_chunk(tb, ua, uW + 16384 * c, c == 0);
                TC_COMMIT(mb + 8 * ((9 + cc) & 3));     // id 9+cc
            }
        }
        wait_commit(mb, 9 + 3 * i + 2);
        TC_FENCE_AFTER();
#pragma unroll
        for (int ch = 0; ch < 2; ch++) {
            int c0 = 32 * half + 16 * ch;
            uint32_t r[16];
            LD16(r, tb + c0 + woff);
            TC_WAIT_LD();
#pragma unroll
            for (int j4 = 0; j4 < 4; j4++) {
                float4 v;
                v.x = __uint_as_float(r[4 * j4 + 0]);
                v.y = __uint_as_float(r[4 * j4 + 1]);
                v.z = __uint_as_float(r[4 * j4 + 2]);
                v.w = __uint_as_float(r[4 * j4 + 3]);
                *reinterpret_cast<float4*>(out1 + (size_t)(t0 + tok) * 384 + i * 128 + c0 + 4 * j4) = v;
            }
        }
        TC_FENCE_BEFORE();
        __syncthreads();
    }

    __syncthreads();
    if (wid == 0) {
        TC_RELINQ();
        TC_DEALLOC(tb, 512);
    }
#endif  // ETP_TC_OK
}

// ============================== launcher ===================================
extern "C" void kernel_launch(void* const* d_in, const int* in_sizes, int n_in,
                              void* d_out, int out_size) {
    (void)in_sizes; (void)n_in; (void)out_size;
    cudaFuncSetAttribute(etp_tc, cudaFuncAttributeMaxDynamicSharedMemorySize,
                         tc::SMEM_BYTES);

    const float* z0  = (const float*)d_in[0];
    const float* z1  = (const float*)d_in[1];
    const float* W0l = (const float*)d_in[2];
    const float* b0l = (const float*)d_in[3];
    const float* W0r = (const float*)d_in[4];
    const float* b0r = (const float*)d_in[5];
    const float* W1l = (const float*)d_in[6];
    const float* W1r = (const float*)d_in[7];
    const float* W0o = (const float*)d_in[8];
    const float* b0o = (const float*)d_in[9];
    const float* W1o = (const float*)d_in[10];

    conv_w<<<144, 256>>>(W0l, W0r, W1l, W1r, W0o, W1o);
    etp_tc<<<tc::NCTA, tc::NT, tc::SMEM_BYTES>>>(z0, z1, b0l, b0r, b0o,
                                                 (float*)d_out);
}

// round 11
// speedup vs baseline: 4.1366x; 1.0383x over previous
#include <cuda_runtime.h>
#include <cuda_bf16.h>
#include <cstdint>

// ===========================================================================
// ElementwiseTensorProducts on tcgen05 (sm_103a), bf16 hi/lo split (3-pass).
// R11: producer/consumer named-barrier split at every MMA issue point —
//      workers bar.arrive and stream ahead; warp 0 bar.sync + issues.
//      Buffer reuse safety rides the existing commit-guard chain.
// ===========================================================================

#if defined(__CUDA_ARCH_FEAT_SM103_ALL) || defined(__CUDA_ARCH_FEAT_SM100_ALL) || \
    defined(__CUDA_ARCH_FEAT_SM101_ALL) || defined(__CUDA_ARCH_SPECIFIC__) ||     \
    defined(__CUDA_ARCH_FAMILY_SPECIFIC__)
#define ETP_TC_OK 1
#endif

#define DI __device__ __forceinline__

namespace tc {
constexpr int BN  = 65536;
constexpr int TOK = 128;
constexpr int NT  = 512;                // 16 warps
constexpr int NCTA = BN / TOK;          // 512

constexpr int OFF_MBAR = 64;            // 4 mbarriers
constexpr int OFF_W    = 1024;          // 3 slots x 16KB hi ; lo at +W_HL
constexpr int W_HL     = 49152;
constexpr int OFF_A    = OFF_W + 2 * W_HL;   // 99328
constexpr int A_HL     = 16384;
constexpr int A_BUF    = 32768;
constexpr int OFF_P0   = OFF_A + 2 * A_BUF;  // 164864
constexpr int P0S      = 129;
constexpr int SMEM_BYTES = OFF_P0 + TOK * P0S * 4;   // 230912

constexpr int CHUNK = 32768;            // bytes per converted weight chunk (hi+lo)

constexpr uint32_t IDESC =
    (1u << 4) | (1u << 7) | (1u << 10) | ((128u / 8) << 17) | ((128u / 16) << 24);

constexpr uint64_t DESC_BASE_SW128 =
    (uint64_t(2) << 61) | (uint64_t(1) << 46) | (uint64_t(64) << 32) | (uint64_t(1) << 16);
}

// Pre-converted weights: 9 chunks x (16KB hi | 16KB lo), SW128-swizzled.
// chunks 0,1: [W0l;W0r] K-halves; 2,3: [W1l;W1r]; 4,5: W0o; 6,7,8: W1o.
__device__ __align__(1024) unsigned char g_W[9 * tc::CHUNK];

DI int swz(int off) { return off ^ ((off >> 3) & 0x70); }

DI void cvt_pack_rn(float x0, float x1, uint32_t& hp, uint32_t& lp) {
    __nv_bfloat16 h0 = __float2bfloat16(x0), h1 = __float2bfloat16(x1);
    float r0 = x0 - __bfloat162float(h0), r1 = x1 - __bfloat162float(h1);
    __nv_bfloat16 l0 = __float2bfloat16(r0), l1 = __float2bfloat16(r1);
    hp = (uint32_t)__bfloat16_as_ushort(h0) | ((uint32_t)__bfloat16_as_ushort(h1) << 16);
    lp = (uint32_t)__bfloat16_as_ushort(l0) | ((uint32_t)__bfloat16_as_ushort(l1) << 16);
}

// ---------------- weight pre-conversion kernel (tiny, runs once/call) ------
__global__ void conv_w(const float* __restrict__ W0l, const float* __restrict__ W0r,
                       const float* __restrict__ W1l, const float* __restrict__ W1r,
                       const float* __restrict__ W0o, const float* __restrict__ W1o) {
    int idx = blockIdx.x * blockDim.x + threadIdx.x;    // 9*4096
    if (idx >= 9 * 4096) return;
    int c  = idx >> 12;
    int r  = (idx >> 5) & 127;
    int kp = idx & 31;
    int k  = ((c >= 6) ? (c - 6) : (c & 1)) * 64 + kp * 2;
    const float* src;
    if (c < 2)      src = (r < 64) ? W0l + r * 128 : W0r + (r - 64) * 128;
    else if (c < 4) src = (r < 64) ? W1l + r * 128 : W1r + (r - 64) * 128;
    else if (c < 6) src = W0o + r * 128;
    else            src = W1o + r * 192;
    float2 v = *reinterpret_cast<const float2*>(src + k);
    uint32_t hp, lp;
    cvt_pack_rn(v.x, v.y, hp, lp);
    int so = c * tc::CHUNK + swz(r * 128 + kp * 4);
    *(uint32_t*)(g_W + so)         = hp;
    *(uint32_t*)(g_W + so + 16384) = lp;
}

DI uint32_t smem_u32(const void* p) {
    uint32_t a;
    asm("{ .reg .u64 t; cvta.to.shared.u64 t, %1; cvt.u32.u64 %0, t; }" : "=r"(a) : "l"(p));
    return a;
}

#ifdef ETP_TC_OK
DI uint32_t elect_one() {
    uint32_t p;
    asm volatile("{ .reg .pred p; elect.sync _|p, 0xFFFFFFFF; selp.b32 %0,1,0,p; }" : "=r"(p));
    return p;
}
#define MBAR_INIT(a, n) \
    asm volatile("mbarrier.init.shared.b64 [%0], %1;" :: "r"(a), "r"(n) : "memory")
#define MBAR_WAIT(a, par) do {                                              \
    uint32_t _m = (a), _p = (par), _d;                                      \
    asm volatile("{ .reg .pred p; mbarrier.try_wait.parity.acquire.cta.shared::cta.b64 p, [%1], %2;" \
                 " selp.b32 %0,1,0,p; }" : "=r"(_d) : "r"(_m), "r"(_p) : "memory");          \
    if (!_d) asm volatile("{ .reg .pred P1; W%=:"                           \
        " mbarrier.try_wait.parity.acquire.cta.shared::cta.b64 P1, [%0], %1, 0x989680;" \
        " @P1 bra.uni D%=; bra.uni W%=; D%=: }" :: "r"(_m), "r"(_p) : "memory"); \
} while (0)
#define TC_ALLOC(sa, n)  asm volatile("tcgen05.alloc.cta_group::1.sync.aligned.shared::cta.b32 [%0], %1;" :: "r"(sa), "r"(n) : "memory")
#define TC_DEALLOC(t, n) asm volatile("tcgen05.dealloc.cta_group::1.sync.aligned.b32 %0, %1;" :: "r"(t), "r"(n))
#define TC_RELINQ()      asm volatile("tcgen05.relinquish_alloc_permit.cta_group::1.sync.aligned;")
#define TC_COMMIT(mb)    asm volatile("tcgen05.commit.cta_group::1.mbarrier::arrive::one.shared::cluster.b64 [%0];" :: "r"(mb) : "memory")
#define TC_WAIT_LD()     asm volatile("tcgen05.wait::ld.sync.aligned;" ::: "memory")
#define TC_FENCE_BEFORE() asm volatile("tcgen05.fence::before_thread_sync;" ::: "memory")
#define TC_FENCE_AFTER()  asm volatile("tcgen05.fence::after_thread_sync;" ::: "memory")
#define FENCE_ASYNC()     asm volatile("fence.proxy.async.shared::cta;" ::: "memory")
#define CP_COMMIT()       asm volatile("cp.async.commit_group;" ::: "memory")
#define CP_WAIT_ALL()     asm volatile("cp.async.wait_group 0;" ::: "memory")
#define BAR_ARR(id)       asm volatile("bar.arrive %0, %1;" :: "r"(id), "r"(tc::NT) : "memory")
#define BAR_SYN(id)       asm volatile("bar.sync %0, %1;"   :: "r"(id), "r"(tc::NT) : "memory")

#define LD16(r, a) \
    asm volatile("tcgen05.ld.sync.aligned.32x32b.x16.b32 " \
        "{%0,%1,%2,%3,%4,%5,%6,%7,%8,%9,%10,%11,%12,%13,%14,%15}, [%16];" \
        : "=r"((r)[0]), "=r"((r)[1]), "=r"((r)[2]), "=r"((r)[3]),   \
          "=r"((r)[4]), "=r"((r)[5]), "=r"((r)[6]), "=r"((r)[7]),   \
          "=r"((r)[8]), "=r"((r)[9]), "=r"((r)[10]), "=r"((r)[11]), \
          "=r"((r)[12]), "=r"((r)[13]), "=r"((r)[14]), "=r"((r)[15]) \
        : "r"(a))

DI uint64_t mkdesc(uint32_t sa) {
    return tc::DESC_BASE_SW128 | (uint64_t(sa >> 4) & 0x3FFF);
}
DI void mma_ss(uint32_t d, uint64_t ad, uint64_t bd, uint32_t en) {
    asm volatile("{ .reg .pred p; setp.ne.u32 p, %4, 0;"
                 " tcgen05.mma.cta_group::1.kind::f16 [%0], %1, %2, %3, {%5,%5,%5,%5}, p; }"
                 :: "r"(d), "l"(ad), "l"(bd), "r"(tc::IDESC), "r"(en), "r"(0u) : "memory");
}
DI void issue_chunk(uint32_t d, uint32_t a, uint32_t w, bool first) {
    uint64_t ah = mkdesc(a), al = mkdesc(a + tc::A_HL);
    uint64_t wh = mkdesc(w), wl = mkdesc(w + tc::W_HL);
#pragma unroll
    for (int s = 0; s < 4; s++) {
        mma_ss(d, ah + 2 * s, wh + 2 * s, (first && s == 0) ? 0u : 1u);
        mma_ss(d, ah + 2 * s, wl + 2 * s, 1u);
        mma_ss(d, al + 2 * s, wh + 2 * s, 1u);
    }
}
DI void wait_commit(uint32_t mb, int idx) {
    MBAR_WAIT(mb + (idx & 3) * 8, (idx >> 2) & 1);
}

// Fast hi/lo split: hi = top 16 bits (truncation), packed via one PRMT;
// lo = exact residual, packed via one cvt.rn.bf16x2.f32.
DI void cvt_store(float x0, float x1, char* dh, char* dl, int so) {
    uint32_t b0 = __float_as_uint(x0), b1 = __float_as_uint(x1);
    uint32_t hp;
    asm("prmt.b32 %0, %1, %2, 0x7632;" : "=r"(hp) : "r"(b0), "r"(b1));
    float h0 = __uint_as_float(b0 & 0xFFFF0000u);
    float h1 = __uint_as_float(b1 & 0xFFFF0000u);
    float l0 = x0 - h0, l1 = x1 - h1;
    uint32_t lp;
    asm("cvt.rn.bf16x2.f32 %0, %1, %2;" : "=r"(lp) : "f"(l1), "f"(l0));
    *(uint32_t*)(dh + so) = hp;
    *(uint32_t*)(dl + so) = lp;
}

// cp.async staging of one converted weight chunk (hi+lo) into W slot
DI void cpa16(uint32_t d, const void* s) {
    asm volatile("cp.async.cg.shared.global [%0], [%1], 16;" :: "r"(d), "l"(s) : "memory");
}
DI void copy_wchunk(uint32_t slot_addr, const unsigned char* g) {
#pragma unroll
    for (int it = 0; it < 16384 / 16 / tc::NT; it++) {
        int off = (threadIdx.x + it * tc::NT) * 16;
        cpa16(slot_addr + off, g + off);                              // hi
        cpa16(slot_addr + tc::W_HL + off, g + 16384 + off);           // lo
    }
}

// ---- fully unrolled activation load/convert (max MLP) ----
template <int ROWS>
DI void ld_regs(const float* __restrict__ g, int gs, float2 (&v)[ROWS * 32 / tc::NT]) {
    constexpr int IT = ROWS * 32 / tc::NT;
#pragma unroll
    for (int it = 0; it < IT; it++) {
        int idx = threadIdx.x + it * tc::NT;
        int row = idx >> 5, kp = idx & 31;
        v[it] = *reinterpret_cast<const float2*>(g + (long long)row * gs + kp * 2);
    }
}
template <int ROWS>
DI void st_regs(const float2 (&v)[ROWS * 32 / tc::NT], char* dh, char* dl) {
    constexpr int IT = ROWS * 32 / tc::NT;
#pragma unroll
    for (int it = 0; it < IT; it++) {
        int idx = threadIdx.x + it * tc::NT;
        int row = idx >> 5, kp = idx & 31;
        cvt_store(v[it].x, v[it].y, dh, dl, swz(row * 128 + kp * 4));
    }
}
#endif  // ETP_TC_OK

__global__ __launch_bounds__(tc::NT, 1) __cluster_dims__(1, 1, 1)
void etp_tc(const float* __restrict__ z0,  const float* __restrict__ z1,
            const float* __restrict__ b0l, const float* __restrict__ b0r,
            const float* __restrict__ b0o, float* __restrict__ out) {
#ifdef ETP_TC_OK
    using namespace tc;
    extern __shared__ char sm[];
    const uint32_t smb = smem_u32(sm);
    const int tid = threadIdx.x, wid = tid >> 5, lane = tid & 31;
    const int t0 = blockIdx.x * TOK;

    char* sA0 = sm + OFF_A;
    char* sA1 = sA0 + A_BUF;
    float* sP0 = reinterpret_cast<float*>(sm + OFF_P0);
    const uint32_t mb = smb + OFF_MBAR;
    const uint32_t uW = smb + OFF_W, uA0 = smb + OFF_A, uA1 = uA0 + A_BUF;
    float* out0 = out;
    float* out1 = out + (size_t)BN * 128;

    if (tid == 0)
        for (int s = 0; s < 4; s++) MBAR_INIT(mb + 8 * s, 1);
    if (wid == 0) TC_ALLOC(smb, 512);

    // ---- stage GEMM1 weights (slots 0,1) ----
    copy_wchunk(uW,          g_W + 0 * CHUNK);
    copy_wchunk(uW + 16384,  g_W + 1 * CHUNK);
    CP_COMMIT();

    __syncthreads();
    uint32_t tb;
    asm volatile("ld.shared.b32 %0, [%1];" : "=r"(tb) : "r"(smb));

    const int subp = wid & 3;                 // TMEM subpartition / token group
    const int half = wid >> 2;                // column quarter 0..3
    const uint32_t woff = (uint32_t)subp << 21;
    const int tok = 32 * subp + lane;

    int bid = 1;                              // named barrier id (1 <-> 2)
    // issue-point macro: workers arrive & stream on; warp0 syncs then issues
#define ISSUE_POINT(BODY) do {                                        \
        FENCE_ASYNC();                                                \
        if (wid == 0) {                                               \
            BAR_SYN(bid);                                             \
            TC_FENCE_AFTER();                                         \
            if (elect_one()) { BODY }                                 \
        } else {                                                      \
            BAR_ARR(bid);                                             \
        }                                                             \
        bid ^= 3;                                                     \
    } while (0)

    // ======== Phase 1: GEMM1 (P0 -> cols 0-127) ========
    {
        float2 v0[8], v1[8];
        ld_regs<128>(z0 + (size_t)t0 * 128,      128, v0);
        ld_regs<128>(z0 + (size_t)t0 * 128 + 64, 128, v1);
        st_regs<128>(v0, sA0, sA0 + A_HL);
        CP_WAIT_ALL();
        ISSUE_POINT( issue_chunk(tb, uA0, uW, true);  TC_COMMIT(mb + 0); );   // id0
        st_regs<128>(v1, sA1, sA1 + A_HL);
        ISSUE_POINT( issue_chunk(tb, uA1, uW + 16384, false); TC_COMMIT(mb + 8); ); // id1
    }

    // stage g2 -> slot2 (free) while GEMM1 runs
    copy_wchunk(uW + 2 * 16384, g_W + 2 * CHUNK);
    CP_COMMIT();

    // ---- P0 drain (+bias); stage g3 -> slot0, g4 -> slot1 ----
    wait_commit(mb, 1);
    TC_FENCE_AFTER();
    copy_wchunk(uW,         g_W + 3 * CHUNK);   // slot0 free (commit1 waited)
    copy_wchunk(uW + 16384, g_W + 4 * CHUNK);   // slot1 free
    CP_COMMIT();
#pragma unroll
    for (int ch = 0; ch < 2; ch++) {
        int c0 = 32 * half + 16 * ch;
        uint32_t r[16];
        LD16(r, tb + c0 + woff);
        TC_WAIT_LD();
#pragma unroll
        for (int j = 0; j < 16; j++) {
            int n = c0 + j;
            float b = (n < 64) ? b0l[n] : b0r[n - 64];
            sP0[tok * P0S + n] = __uint_as_float(r[j]) + b;
        }
    }

    // ======== Phase 2: GEMM2 (P1_i -> cols 128+128i); W: c0->slot2, c1->slot0
    for (int i = 0; i < 3; i++)
#pragma unroll 1
        for (int c = 0; c < 2; c++) {
            int cc = 2 * i + c;
            char* ab = (cc & 1) ? sA1 : sA0;
            uint32_t ua = (cc & 1) ? uA1 : uA0;
            float2 v[8];
            ld_regs<128>(z1 + (size_t)t0 * 384 + i * 128 + 64 * c, 384, v);
            if (cc >= 2) wait_commit(mb, cc);       // A-buffer guard
            st_regs<128>(v, ab, ab + A_HL);
            if (cc == 0) CP_WAIT_ALL();             // g2,g3 staged before first use
            ISSUE_POINT(
                issue_chunk(tb + 128 + 128 * i, ua, uW + 16384 * (c == 0 ? 2 : 0), c == 0);
                TC_COMMIT(mb + 8 * ((2 + cc) & 3));     // id 2+cc
            );
        }

    // slot2's last MMA use is id6 -> stage g5 -> slot2
    wait_commit(mb, 6);
    copy_wchunk(uW + 2 * 16384, g_W + 5 * CHUNK);
    CP_COMMIT();

    // ======== Phase 3: Y0 + GEMM3 + out0 ========
    wait_commit(mb, 7);
    TC_FENCE_AFTER();
    {
        const float* p0r = sP0 + tok * P0S;
        const int r0 = 16 * half;
        float s[16];
#pragma unroll
        for (int j = 0; j < 16; j++) s[j] = 0.f;
#pragma unroll
        for (int i = 0; i < 3; i++) {
            uint32_t lv[16], rv[16];
            LD16(lv, tb + 128 + 128 * i + r0 + woff);
            LD16(rv, tb + 128 + 128 * i + 64 + r0 + woff);
            TC_WAIT_LD();
#pragma unroll
            for (int j = 0; j < 16; j++)
                s[j] += __uint_as_float(lv[j]) * __uint_as_float(rv[j]);
        }
#pragma unroll
        for (int j = 0; j < 16; j += 2) {
            int k = r0 + j;
            float a0 = p0r[k] * p0r[64 + k];
            float a1 = p0r[k + 1] * p0r[64 + k + 1];
            cvt_store(a0, a1, sA0, sA0 + A_HL, swz(tok * 128 + 2 * k));
            cvt_store(s[j], s[j + 1], sA1, sA1 + A_HL, swz(tok * 128 + 2 * k));
        }
    }
    CP_WAIT_ALL();
    TC_FENCE_BEFORE();
    ISSUE_POINT(
        issue_chunk(tb, uA0, uW + 16384,     true);   // g4 = W0o chunk0 (slot1)
        issue_chunk(tb, uA1, uW + 2 * 16384, false);  // g5 = W0o chunk1 (slot2)
        TC_COMMIT(mb + 0);                            // id8
    );
    copy_wchunk(uW, g_W + 6 * CHUNK);                 // g6 -> slot0 (free after id7)
    CP_COMMIT();

    wait_commit(mb, 8);
    TC_FENCE_AFTER();
#pragma unroll
    for (int ch = 0; ch < 2; ch++) {
        int c0 = 32 * half + 16 * ch;
        uint32_t r[16];
        LD16(r, tb + c0 + woff);
        TC_WAIT_LD();
#pragma unroll
        for (int j4 = 0; j4 < 4; j4++) {
            float4 v;
            v.x = __uint_as_float(r[4 * j4 + 0]) + b0o[c0 + 4 * j4 + 0];
            v.y = __uint_as_float(r[4 * j4 + 1]) + b0o[c0 + 4 * j4 + 1];
            v.z = __uint_as_float(r[4 * j4 + 2]) + b0o[c0 + 4 * j4 + 2];
            v.w = __uint_as_float(r[4 * j4 + 3]) + b0o[c0 + 4 * j4 + 3];
            *reinterpret_cast<float4*>(out0 + (size_t)(t0 + tok) * 128 + c0 + 4 * j4) = v;
        }
    }
    copy_wchunk(uW + 16384,     g_W + 7 * CHUNK);     // g7 -> slot1 (free after id8)
    copy_wchunk(uW + 2 * 16384, g_W + 8 * CHUNK);     // g8 -> slot2
    CP_COMMIT();

    // ======== Phase 4: per component: Y1_i + GEMM4_i + out1_i ========
#pragma unroll 1
    for (int i = 0; i < 3; i++) {
        const int i1 = (i + 1 == 3) ? 0 : i + 1;
        const int i2 = (i + 2 >= 3) ? i - 1 : i + 2;
        const float* p0r = sP0 + tok * P0S;
        const int r0 = 16 * half;
#pragma unroll 1
        for (int c = 0; c < 3; c++) {
            int cc = 3 * i + c;
            char* ab = (cc & 1) ? sA1 : sA0;
            uint32_t ua = (cc & 1) ? uA1 : uA0;
            float y[16];
            if (c == 0) {                 // q011 = z0_l * z1_r[i]
                uint32_t rv[16];
                LD16(rv, tb + 128 + 128 * i + 64 + r0 + woff);
                TC_WAIT_LD();
#pragma unroll
                for (int j = 0; j < 16; j++)
                    y[j] = p0r[r0 + j] * __uint_as_float(rv[j]);
            } else if (c == 1) {          // q101 = z1_l[i] * z0_r
                uint32_t lv[16];
                LD16(lv, tb + 128 + 128 * i + r0 + woff);
                TC_WAIT_LD();
#pragma unroll
                for (int j = 0; j < 16; j++)
                    y[j] = __uint_as_float(lv[j]) * p0r[64 + r0 + j];
            } else {                      // q111 = l_i1*r_i2 - l_i2*r_i1
                uint32_t va[16], vb[16];
                LD16(va, tb + 128 + 128 * i1 + r0 + woff);
                LD16(vb, tb + 128 + 128 * i2 + 64 + r0 + woff);
                TC_WAIT_LD();
#pragma unroll
                for (int j = 0; j < 16; j++)
                    y[j] = __uint_as_float(va[j]) * __uint_as_float(vb[j]);
                LD16(va, tb + 128 + 128 * i2 + r0 + woff);
                LD16(vb, tb + 128 + 128 * i1 + 64 + r0 + woff);
                TC_WAIT_LD();
#pragma unroll
                for (int j = 0; j < 16; j++)
                    y[j] -= __uint_as_float(va[j]) * __uint_as_float(vb[j]);
            }
            if (cc >= 2) wait_commit(mb, 9 + cc - 2);   // A-buffer guard
#pragma unroll
            for (int j = 0; j < 16; j += 2)
                cvt_store(y[j], y[j + 1], ab, ab + A_HL,
                          swz(tok * 128 + 2 * (r0 + j)));
            if (cc == 0) CP_WAIT_ALL();                 // g6..g8 staged
            TC_FENCE_BEFORE();
            ISSUE_POINT(
                issue_chunk(tb, ua, uW + 16384 * c, c == 0);
                TC_COMMIT(mb + 8 * ((9 + cc) & 3));     // id 9+cc
            );
        }
        wait_commit(mb, 9 + 3 * i + 2);
        TC_FENCE_AFTER();
#pragma unroll
        for (int ch = 0; ch < 2; ch++) {
            int c0 = 32 * half + 16 * ch;
            uint32_t r[16];
            LD16(r, tb + c0 + woff);
            TC_WAIT_LD();
#pragma unroll
            for (int j4 = 0; j4 < 4; j4++) {
                float4 v;
                v.x = __uint_as_float(r[4 * j4 + 0]);
                v.y = __uint_as_float(r[4 * j4 + 1]);
                v.z = __uint_as_float(r[4 * j4 + 2]);
                v.w = __uint_as_float(r[4 * j4 + 3]);
                *reinterpret_cast<float4*>(out1 + (size_t)(t0 + tok) * 384 + i * 128 + c0 + 4 * j4) = v;
            }
        }
        TC_FENCE_BEFORE();
        // drain completion is signaled to the issuer via the next issue
        // point's arrivals (each warp arrives only after its drain reads).
    }

    __syncthreads();
    if (wid == 0) {
        TC_RELINQ();
        TC_DEALLOC(tb, 512);
    }
#undef ISSUE_POINT
#endif  // ETP_TC_OK
}

// ============================== launcher ===================================
extern "C" void kernel_launch(void* const* d_in, const int* in_sizes, int n_in,
                              void* d_out, int out_size) {
    (void)in_sizes; (void)n_in; (void)out_size;
    cudaFuncSetAttribute(etp_tc, cudaFuncAttributeMaxDynamicSharedMemorySize,
                         tc::SMEM_BYTES);

    const float* z0  = (const float*)d_in[0];
    const float* z1  = (const float*)d_in[1];
    const float* W0l = (const float*)d_in[2];
    const float* b0l = (const float*)d_in[3];
    const float* W0r = (const float*)d_in[4];
    const float* b0r = (const float*)d_in[5];
    const float* W1l = (const float*)d_in[6];
    const float* W1r = (const float*)d_in[7];
    const float* W0o = (const float*)d_in[8];
    const float* b0o = (const float*)d_in[9];
    const float* W1o = (const float*)d_in[10];

    conv_w<<<144, 256>>>(W0l, W0r, W1l, W1r, W0o, W1o);
    etp_tc<<<tc::NCTA, tc::NT, tc::SMEM_BYTES>>>(z0, z1, b0l, b0r, b0o,
                                                 (float*)d_out);
}

// round 16
// speedup vs baseline: 4.1465x; 1.0024x over previous
#include <cuda_runtime.h>
#include <cuda_bf16.h>
#include <cstdint>

// ===========================================================================
// ElementwiseTensorProducts on tcgen05 (sm_103a), bf16 hi/lo split (3-pass).
// R16: R11 schedule (174.6us proven) with ONLY the x32-LDTM drain change.
// Phase-3 split waits from R12 reverted (suspected hang cause).
// ===========================================================================

#if defined(__CUDA_ARCH_FEAT_SM103_ALL) || defined(__CUDA_ARCH_FEAT_SM100_ALL) || \
    defined(__CUDA_ARCH_FEAT_SM101_ALL) || defined(__CUDA_ARCH_SPECIFIC__) ||     \
    defined(__CUDA_ARCH_FAMILY_SPECIFIC__)
#define ETP_TC_OK 1
#endif

#define DI __device__ __forceinline__

namespace tc {
constexpr int BN  = 65536;
constexpr int TOK = 128;
constexpr int NT  = 512;                // 16 warps
constexpr int NCTA = BN / TOK;          // 512

constexpr int OFF_MBAR = 64;            // 4 mbarriers
constexpr int OFF_W    = 1024;          // 3 slots x 16KB hi ; lo at +W_HL
constexpr int W_HL     = 49152;
constexpr int OFF_A    = OFF_W + 2 * W_HL;   // 99328
constexpr int A_HL     = 16384;
constexpr int A_BUF    = 32768;
constexpr int OFF_P0   = OFF_A + 2 * A_BUF;  // 164864
constexpr int P0S      = 129;
constexpr int SMEM_BYTES = OFF_P0 + TOK * P0S * 4;   // 230912

constexpr int CHUNK = 32768;            // bytes per converted weight chunk (hi+lo)

constexpr uint32_t IDESC =
    (1u << 4) | (1u << 7) | (1u << 10) | ((128u / 8) << 17) | ((128u / 16) << 24);

constexpr uint64_t DESC_BASE_SW128 =
    (uint64_t(2) << 61) | (uint64_t(1) << 46) | (uint64_t(64) << 32) | (uint64_t(1) << 16);
}

// Pre-converted weights: 9 chunks x (16KB hi | 16KB lo), SW128-swizzled.
// chunks 0,1: [W0l;W0r] K-halves; 2,3: [W1l;W1r]; 4,5: W0o; 6,7,8: W1o.
__device__ __align__(1024) unsigned char g_W[9 * tc::CHUNK];

DI int swz(int off) { return off ^ ((off >> 3) & 0x70); }

DI void cvt_pack_rn(float x0, float x1, uint32_t& hp, uint32_t& lp) {
    __nv_bfloat16 h0 = __float2bfloat16(x0), h1 = __float2bfloat16(x1);
    float r0 = x0 - __bfloat162float(h0), r1 = x1 - __bfloat162float(h1);
    __nv_bfloat16 l0 = __float2bfloat16(r0), l1 = __float2bfloat16(r1);
    hp = (uint32_t)__bfloat16_as_ushort(h0) | ((uint32_t)__bfloat16_as_ushort(h1) << 16);
    lp = (uint32_t)__bfloat16_as_ushort(l0) | ((uint32_t)__bfloat16_as_ushort(l1) << 16);
}

// ---------------- weight pre-conversion kernel (tiny, runs once/call) ------
__global__ void conv_w(const float* __restrict__ W0l, const float* __restrict__ W0r,
                       const float* __restrict__ W1l, const float* __restrict__ W1r,
                       const float* __restrict__ W0o, const float* __restrict__ W1o) {
    int idx = blockIdx.x * blockDim.x + threadIdx.x;    // 9*4096
    if (idx >= 9 * 4096) return;
    int c  = idx >> 12;
    int r  = (idx >> 5) & 127;
    int kp = idx & 31;
    int k  = ((c >= 6) ? (c - 6) : (c & 1)) * 64 + kp * 2;
    const float* src;
    if (c < 2)      src = (r < 64) ? W0l + r * 128 : W0r + (r - 64) * 128;
    else if (c < 4) src = (r < 64) ? W1l + r * 128 : W1r + (r - 64) * 128;
    else if (c < 6) src = W0o + r * 128;
    else            src = W1o + r * 192;
    float2 v = *reinterpret_cast<const float2*>(src + k);
    uint32_t hp, lp;
    cvt_pack_rn(v.x, v.y, hp, lp);
    int so = c * tc::CHUNK + swz(r * 128 + kp * 4);
    *(uint32_t*)(g_W + so)         = hp;
    *(uint32_t*)(g_W + so + 16384) = lp;
}

DI uint32_t smem_u32(const void* p) {
    uint32_t a;
    asm("{ .reg .u64 t; cvta.to.shared.u64 t, %1; cvt.u32.u64 %0, t; }" : "=r"(a) : "l"(p));
    return a;
}

#ifdef ETP_TC_OK
DI uint32_t elect_one() {
    uint32_t p;
    asm volatile("{ .reg .pred p; elect.sync _|p, 0xFFFFFFFF; selp.b32 %0,1,0,p; }" : "=r"(p));
    return p;
}
#define MBAR_INIT(a, n) \
    asm volatile("mbarrier.init.shared.b64 [%0], %1;" :: "r"(a), "r"(n) : "memory")
#define MBAR_WAIT(a, par) do {                                              \
    uint32_t _m = (a), _p = (par), _d;                                      \
    asm volatile("{ .reg .pred p; mbarrier.try_wait.parity.acquire.cta.shared::cta.b64 p, [%1], %2;" \
                 " selp.b32 %0,1,0,p; }" : "=r"(_d) : "r"(_m), "r"(_p) : "memory");          \
    if (!_d) asm volatile("{ .reg .pred P1; W%=:"                           \
        " mbarrier.try_wait.parity.acquire.cta.shared::cta.b64 P1, [%0], %1, 0x989680;" \
        " @P1 bra.uni D%=; bra.uni W%=; D%=: }" :: "r"(_m), "r"(_p) : "memory"); \
} while (0)
#define TC_ALLOC(sa, n)  asm volatile("tcgen05.alloc.cta_group::1.sync.aligned.shared::cta.b32 [%0], %1;" :: "r"(sa), "r"(n) : "memory")
#define TC_DEALLOC(t, n) asm volatile("tcgen05.dealloc.cta_group::1.sync.aligned.b32 %0, %1;" :: "r"(t), "r"(n))
#define TC_RELINQ()      asm volatile("tcgen05.relinquish_alloc_permit.cta_group::1.sync.aligned;")
#define TC_COMMIT(mb)    asm volatile("tcgen05.commit.cta_group::1.mbarrier::arrive::one.shared::cluster.b64 [%0];" :: "r"(mb) : "memory")
#define TC_WAIT_LD()     asm volatile("tcgen05.wait::ld.sync.aligned;" ::: "memory")
#define TC_FENCE_BEFORE() asm volatile("tcgen05.fence::before_thread_sync;" ::: "memory")
#define TC_FENCE_AFTER()  asm volatile("tcgen05.fence::after_thread_sync;" ::: "memory")
#define FENCE_ASYNC()     asm volatile("fence.proxy.async.shared::cta;" ::: "memory")
#define CP_COMMIT()       asm volatile("cp.async.commit_group;" ::: "memory")
#define CP_WAIT_ALL()     asm volatile("cp.async.wait_group 0;" ::: "memory")
#define BAR_ARR(id)       asm volatile("bar.arrive %0, %1;" :: "r"(id), "r"(tc::NT) : "memory")
#define BAR_SYN(id)       asm volatile("bar.sync %0, %1;"   :: "r"(id), "r"(tc::NT) : "memory")

#define LD16(r, a) \
    asm volatile("tcgen05.ld.sync.aligned.32x32b.x16.b32 " \
        "{%0,%1,%2,%3,%4,%5,%6,%7,%8,%9,%10,%11,%12,%13,%14,%15}, [%16];" \
        : "=r"((r)[0]), "=r"((r)[1]), "=r"((r)[2]), "=r"((r)[3]),   \
          "=r"((r)[4]), "=r"((r)[5]), "=r"((r)[6]), "=r"((r)[7]),   \
          "=r"((r)[8]), "=r"((r)[9]), "=r"((r)[10]), "=r"((r)[11]), \
          "=r"((r)[12]), "=r"((r)[13]), "=r"((r)[14]), "=r"((r)[15]) \
        : "r"(a))

#define LD32(r, a) \
    asm volatile("tcgen05.ld.sync.aligned.32x32b.x32.b32 " \
        "{%0,%1,%2,%3,%4,%5,%6,%7,%8,%9,%10,%11,%12,%13,%14,%15," \
        " %16,%17,%18,%19,%20,%21,%22,%23,%24,%25,%26,%27,%28,%29,%30,%31}, [%32];" \
        : "=r"((r)[0]),  "=r"((r)[1]),  "=r"((r)[2]),  "=r"((r)[3]),  \
          "=r"((r)[4]),  "=r"((r)[5]),  "=r"((r)[6]),  "=r"((r)[7]),  \
          "=r"((r)[8]),  "=r"((r)[9]),  "=r"((r)[10]), "=r"((r)[11]), \
          "=r"((r)[12]), "=r"((r)[13]), "=r"((r)[14]), "=r"((r)[15]), \
          "=r"((r)[16]), "=r"((r)[17]), "=r"((r)[18]), "=r"((r)[19]), \
          "=r"((r)[20]), "=r"((r)[21]), "=r"((r)[22]), "=r"((r)[23]), \
          "=r"((r)[24]), "=r"((r)[25]), "=r"((r)[26]), "=r"((r)[27]), \
          "=r"((r)[28]), "=r"((r)[29]), "=r"((r)[30]), "=r"((r)[31]) \
        : "r"(a))

DI uint64_t mkdesc(uint32_t sa) {
    return tc::DESC_BASE_SW128 | (uint64_t(sa >> 4) & 0x3FFF);
}
DI void mma_ss(uint32_t d, uint64_t ad, uint64_t bd, uint32_t en) {
    asm volatile("{ .reg .pred p; setp.ne.u32 p, %4, 0;"
                 " tcgen05.mma.cta_group::1.kind::f16 [%0], %1, %2, %3, {%5,%5,%5,%5}, p; }"
                 :: "r"(d), "l"(ad), "l"(bd), "r"(tc::IDESC), "r"(en), "r"(0u) : "memory");
}
DI void issue_chunk(uint32_t d, uint32_t a, uint32_t w, bool first) {
    uint64_t ah = mkdesc(a), al = mkdesc(a + tc::A_HL);
    uint64_t wh = mkdesc(w), wl = mkdesc(w + tc::W_HL);
#pragma unroll
    for (int s = 0; s < 4; s++) {
        mma_ss(d, ah + 2 * s, wh + 2 * s, (first && s == 0) ? 0u : 1u);
        mma_ss(d, ah + 2 * s, wl + 2 * s, 1u);
        mma_ss(d, al + 2 * s, wh + 2 * s, 1u);
    }
}
DI void wait_commit(uint32_t mb, int idx) {
    MBAR_WAIT(mb + (idx & 3) * 8, (idx >> 2) & 1);
}

// Fast hi/lo split: hi = top 16 bits (truncation), packed via one PRMT;
// lo = exact residual, packed via one cvt.rn.bf16x2.f32.
DI void cvt_store(float x0, float x1, char* dh, char* dl, int so) {
    uint32_t b0 = __float_as_uint(x0), b1 = __float_as_uint(x1);
    uint32_t hp;
    asm("prmt.b32 %0, %1, %2, 0x7632;" : "=r"(hp) : "r"(b0), "r"(b1));
    float h0 = __uint_as_float(b0 & 0xFFFF0000u);
    float h1 = __uint_as_float(b1 & 0xFFFF0000u);
    float l0 = x0 - h0, l1 = x1 - h1;
    uint32_t lp;
    asm("cvt.rn.bf16x2.f32 %0, %1, %2;" : "=r"(lp) : "f"(l1), "f"(l0));
    *(uint32_t*)(dh + so) = hp;
    *(uint32_t*)(dl + so) = lp;
}

// cp.async staging of one converted weight chunk (hi+lo) into W slot
DI void cpa16(uint32_t d, const void* s) {
    asm volatile("cp.async.cg.shared.global [%0], [%1], 16;" :: "r"(d), "l"(s) : "memory");
}
DI void copy_wchunk(uint32_t slot_addr, const unsigned char* g) {
#pragma unroll
    for (int it = 0; it < 16384 / 16 / tc::NT; it++) {
        int off = (threadIdx.x + it * tc::NT) * 16;
        cpa16(slot_addr + off, g + off);                              // hi
        cpa16(slot_addr + tc::W_HL + off, g + 16384 + off);           // lo
    }
}

// ---- fully unrolled activation load/convert (max MLP) ----
template <int ROWS>
DI void ld_regs(const float* __restrict__ g, int gs, float2 (&v)[ROWS * 32 / tc::NT]) {
    constexpr int IT = ROWS * 32 / tc::NT;
#pragma unroll
    for (int it = 0; it < IT; it++) {
        int idx = threadIdx.x + it * tc::NT;
        int row = idx >> 5, kp = idx & 31;
        v[it] = *reinterpret_cast<const float2*>(g + (long long)row * gs + kp * 2);
    }
}
template <int ROWS>
DI void st_regs(const float2 (&v)[ROWS * 32 / tc::NT], char* dh, char* dl) {
    constexpr int IT = ROWS * 32 / tc::NT;
#pragma unroll
    for (int it = 0; it < IT; it++) {
        int idx = threadIdx.x + it * tc::NT;
        int row = idx >> 5, kp = idx & 31;
        cvt_store(v[it].x, v[it].y, dh, dl, swz(row * 128 + kp * 4));
    }
}
#endif  // ETP_TC_OK

__global__ __launch_bounds__(tc::NT, 1) __cluster_dims__(1, 1, 1)
void etp_tc(const float* __restrict__ z0,  const float* __restrict__ z1,
            const float* __restrict__ b0l, const float* __restrict__ b0r,
            const float* __restrict__ b0o, float* __restrict__ out) {
#ifdef ETP_TC_OK
    using namespace tc;
    extern __shared__ char sm[];
    const uint32_t smb = smem_u32(sm);
    const int tid = threadIdx.x, wid = tid >> 5, lane = tid & 31;
    const int t0 = blockIdx.x * TOK;

    char* sA0 = sm + OFF_A;
    char* sA1 = sA0 + A_BUF;
    float* sP0 = reinterpret_cast<float*>(sm + OFF_P0);
    const uint32_t mb = smb + OFF_MBAR;
    const uint32_t uW = smb + OFF_W, uA0 = smb + OFF_A, uA1 = uA0 + A_BUF;
    float* out0 = out;
    float* out1 = out + (size_t)BN * 128;

    if (tid == 0)
        for (int s = 0; s < 4; s++) MBAR_INIT(mb + 8 * s, 1);
    if (wid == 0) TC_ALLOC(smb, 512);

    // ---- stage GEMM1 weights (slots 0,1) ----
    copy_wchunk(uW,          g_W + 0 * CHUNK);
    copy_wchunk(uW + 16384,  g_W + 1 * CHUNK);
    CP_COMMIT();

    __syncthreads();
    uint32_t tb;
    asm volatile("ld.shared.b32 %0, [%1];" : "=r"(tb) : "r"(smb));

    const int subp = wid & 3;                 // TMEM subpartition / token group
    const int half = wid >> 2;                // column quarter 0..3
    const uint32_t woff = (uint32_t)subp << 21;
    const int tok = 32 * subp + lane;

    int bid = 1;                              // named barrier id (1 <-> 2)
#define ISSUE_POINT(BODY) do {                                        \
        FENCE_ASYNC();                                                \
        if (wid == 0) {                                               \
            BAR_SYN(bid);                                             \
            TC_FENCE_AFTER();                                         \
            if (elect_one()) { BODY }                                 \
        } else {                                                      \
            BAR_ARR(bid);                                             \
        }                                                             \
        bid ^= 3;                                                     \
    } while (0)

    // ======== Phase 1: GEMM1 (P0 -> cols 0-127) ========
    {
        float2 v0[8], v1[8];
        ld_regs<128>(z0 + (size_t)t0 * 128,      128, v0);
        ld_regs<128>(z0 + (size_t)t0 * 128 + 64, 128, v1);
        st_regs<128>(v0, sA0, sA0 + A_HL);
        CP_WAIT_ALL();
        ISSUE_POINT( issue_chunk(tb, uA0, uW, true);  TC_COMMIT(mb + 0); );   // id0
        st_regs<128>(v1, sA1, sA1 + A_HL);
        ISSUE_POINT( issue_chunk(tb, uA1, uW + 16384, false); TC_COMMIT(mb + 8); ); // id1
    }

    // stage g2 -> slot2 (free) while GEMM1 runs
    copy_wchunk(uW + 2 * 16384, g_W + 2 * CHUNK);
    CP_COMMIT();

    // ---- P0 drain (+bias); stage g3 -> slot0, g4 -> slot1 ----
    wait_commit(mb, 1);
    TC_FENCE_AFTER();
    copy_wchunk(uW,         g_W + 3 * CHUNK);   // slot0 free (commit1 waited)
    copy_wchunk(uW + 16384, g_W + 4 * CHUNK);   // slot1 free
    CP_COMMIT();
    {
        uint32_t r[32];
        LD32(r, tb + 32 * half + woff);
        TC_WAIT_LD();
#pragma unroll
        for (int j = 0; j < 32; j++) {
            int n = 32 * half + j;
            float b = (n < 64) ? b0l[n] : b0r[n - 64];
            sP0[tok * P0S + n] = __uint_as_float(r[j]) + b;
        }
    }

    // ======== Phase 2: GEMM2 (P1_i -> cols 128+128i); W: c0->slot2, c1->slot0
    for (int i = 0; i < 3; i++)
#pragma unroll 1
        for (int c = 0; c < 2; c++) {
            int cc = 2 * i + c;
            char* ab = (cc & 1) ? sA1 : sA0;
            uint32_t ua = (cc & 1) ? uA1 : uA0;
            float2 v[8];
            ld_regs<128>(z1 + (size_t)t0 * 384 + i * 128 + 64 * c, 384, v);
            if (cc >= 2) wait_commit(mb, cc);       // A-buffer guard
            st_regs<128>(v, ab, ab + A_HL);
            if (cc == 0) CP_WAIT_ALL();             // g2,g3 staged before first use
            ISSUE_POINT(
                issue_chunk(tb + 128 + 128 * i, ua, uW + 16384 * (c == 0 ? 2 : 0), c == 0);
                TC_COMMIT(mb + 8 * ((2 + cc) & 3));     // id 2+cc
            );
        }

    // slot2's last MMA use is id6 -> stage g5 -> slot2
    wait_commit(mb, 6);
    copy_wchunk(uW + 2 * 16384, g_W + 5 * CHUNK);
    CP_COMMIT();

    // ======== Phase 3: Y0 + GEMM3 + out0 (single wait at id7, R11-proven) ===
    wait_commit(mb, 7);
    TC_FENCE_AFTER();
    {
        const float* p0r = sP0 + tok * P0S;
        const int r0 = 16 * half;
        float s[16];
#pragma unroll
        for (int j = 0; j < 16; j++) s[j] = 0.f;
#pragma unroll
        for (int i = 0; i < 3; i++) {
            uint32_t lv[16], rv[16];
            LD16(lv, tb + 128 + 128 * i + r0 + woff);
            LD16(rv, tb + 128 + 128 * i + 64 + r0 + woff);
            TC_WAIT_LD();
#pragma unroll
            for (int j = 0; j < 16; j++)
                s[j] += __uint_as_float(lv[j]) * __uint_as_float(rv[j]);
        }
#pragma unroll
        for (int j = 0; j < 16; j += 2) {
            int k = r0 + j;
            float a0 = p0r[k] * p0r[64 + k];
            float a1 = p0r[k + 1] * p0r[64 + k + 1];
            cvt_store(a0, a1, sA0, sA0 + A_HL, swz(tok * 128 + 2 * k));
            cvt_store(s[j], s[j + 1], sA1, sA1 + A_HL, swz(tok * 128 + 2 * k));
        }
    }
    CP_WAIT_ALL();
    TC_FENCE_BEFORE();
    ISSUE_POINT(
        issue_chunk(tb, uA0, uW + 16384,     true);   // g4 = W0o chunk0 (slot1)
        issue_chunk(tb, uA1, uW + 2 * 16384, false);  // g5 = W0o chunk1 (slot2)
        TC_COMMIT(mb + 0);                            // id8
    );
    copy_wchunk(uW, g_W + 6 * CHUNK);                 // g6 -> slot0 (free after id7)
    CP_COMMIT();

    wait_commit(mb, 8);
    TC_FENCE_AFTER();
    {
        uint32_t r[32];
        LD32(r, tb + 32 * half + woff);
        TC_WAIT_LD();
#pragma unroll
        for (int j4 = 0; j4 < 8; j4++) {
            int c0 = 32 * half + 4 * j4;
            float4 v;
            v.x = __uint_as_float(r[4 * j4 + 0]) + b0o[c0 + 0];
            v.y = __uint_as_float(r[4 * j4 + 1]) + b0o[c0 + 1];
            v.z = __uint_as_float(r[4 * j4 + 2]) + b0o[c0 + 2];
            v.w = __uint_as_float(r[4 * j4 + 3]) + b0o[c0 + 3];
            *reinterpret_cast<float4*>(out0 + (size_t)(t0 + tok) * 128 + c0) = v;
        }
    }
    copy_wchunk(uW + 16384,     g_W + 7 * CHUNK);     // g7 -> slot1 (free after id8)
    copy_wchunk(uW + 2 * 16384, g_W + 8 * CHUNK);     // g8 -> slot2
    CP_COMMIT();

    // ======== Phase 4: per component: Y1_i + GEMM4_i + out1_i ========
#pragma unroll 1
    for (int i = 0; i < 3; i++) {
        const int i1 = (i + 1 == 3) ? 0 : i + 1;
        const int i2 = (i + 2 >= 3) ? i - 1 : i + 2;
        const float* p0r = sP0 + tok * P0S;
        const int r0 = 16 * half;
#pragma unroll 1
        for (int c = 0; c < 3; c++) {
            int cc = 3 * i + c;
            char* ab = (cc & 1) ? sA1 : sA0;
            uint32_t ua = (cc & 1) ? uA1 : uA0;
            float y[16];
            if (c == 0) {                 // q011 = z0_l * z1_r[i]
                uint32_t rv[16];
                LD16(rv, tb + 128 + 128 * i + 64 + r0 + woff);
                TC_WAIT_LD();
#pragma unroll
                for (int j = 0; j < 16; j++)
                    y[j] = p0r[r0 + j] * __uint_as_float(rv[j]);
            } else if (c == 1) {          // q101 = z1_l[i] * z0_r
                uint32_t lv[16];
                LD16(lv, tb + 128 + 128 * i + r0 + woff);
                TC_WAIT_LD();
#pragma unroll
                for (int j = 0; j < 16; j++)
                    y[j] = __uint_as_float(lv[j]) * p0r[64 + r0 + j];
            } else {                      // q111 = l_i1*r_i2 - l_i2*r_i1
                uint32_t va[16], vb[16];
                LD16(va, tb + 128 + 128 * i1 + r0 + woff);
                LD16(vb, tb + 128 + 128 * i2 + 64 + r0 + woff);
                TC_WAIT_LD();
#pragma unroll
                for (int j = 0; j < 16; j++)
                    y[j] = __uint_as_float(va[j]) * __uint_as_float(vb[j]);
                LD16(va, tb + 128 + 128 * i2 + r0 + woff);
                LD16(vb, tb + 128 + 128 * i1 + 64 + r0 + woff);
                TC_WAIT_LD();
#pragma unroll
                for (int j = 0; j < 16; j++)
                    y[j] -= __uint_as_float(va[j]) * __uint_as_float(vb[j]);
            }
            if (cc >= 2) wait_commit(mb, 9 + cc - 2);   // A-buffer guard
#pragma unroll
            for (int j = 0; j < 16; j += 2)
                cvt_store(y[j], y[j + 1], ab, ab + A_HL,
                          swz(tok * 128 + 2 * (r0 + j)));
            if (cc == 0) CP_WAIT_ALL();                 // g6..g8 staged
            TC_FENCE_BEFORE();
            ISSUE_POINT(
                issue_chunk(tb, ua, uW + 16384 * c, c == 0);
                TC_COMMIT(mb + 8 * ((9 + cc) & 3));     // id 9+cc
            );
        }
        wait_commit(mb, 9 + 3 * i + 2);
        TC_FENCE_AFTER();
        {
            uint32_t r[32];
            LD32(r, tb + 32 * half + woff);
            TC_WAIT_LD();
#pragma unroll
            for (int j4 = 0; j4 < 8; j4++) {
                int c0 = 32 * half + 4 * j4;
                float4 v;
                v.x = __uint_as_float(r[4 * j4 + 0]);
                v.y = __uint_as_float(r[4 * j4 + 1]);
                v.z = __uint_as_float(r[4 * j4 + 2]);
                v.w = __uint_as_float(r[4 * j4 + 3]);
                *reinterpret_cast<float4*>(out1 + (size_t)(t0 + tok) * 384 + i * 128 + c0) = v;
            }
        }
        TC_FENCE_BEFORE();
        // drain completion is signaled to the issuer via the next issue
        // point's arrivals (each warp arrives only after its drain reads).
    }

    __syncthreads();
    if (wid == 0) {
        TC_RELINQ();
        TC_DEALLOC(tb, 512);
    }
#undef ISSUE_POINT
#endif  // ETP_TC_OK
}

// ============================== launcher ===================================
extern "C" void kernel_launch(void* const* d_in, const int* in_sizes, int n_in,
                              void* d_out, int out_size) {
    (void)in_sizes; (void)n_in; (void)out_size;
    cudaFuncSetAttribute(etp_tc, cudaFuncAttributeMaxDynamicSharedMemorySize,
                         tc::SMEM_BYTES);

    const float* z0  = (const float*)d_in[0];
    const float* z1  = (const float*)d_in[1];
    const float* W0l = (const float*)d_in[2];
    const float* b0l = (const float*)d_in[3];
    const float* W0r = (const float*)d_in[4];
    const float* b0r = (const float*)d_in[5];
    const float* W1l = (const float*)d_in[6];
    const float* W1r = (const float*)d_in[7];
    const float* W0o = (const float*)d_in[8];
    const float* b0o = (const float*)d_in[9];
    const float* W1o = (const float*)d_in[10];

    conv_w<<<144, 256>>>(W0l, W0r, W1l, W1r, W0o, W1o);
    etp_tc<<<tc::NCTA, tc::NT, tc::SMEM_BYTES>>>(z0, z1, b0l, b0r, b0o,
                                                 (float*)d_out);
}